// round 13
// baseline (speedup 1.0000x reference)
#include <cuda_runtime.h>
#include <cuda_fp16.h>
#include <math.h>

// Problem constants
#define BB  2
#define TT  1024
#define DD  1024
#define HH  16
#define HDD 64
#define LL  3
#define VV  32000
#define FFD 4096
#define BT  (BB*TT)

#define BM 128
#define BN 128
#define BK 32
#define NS 3            // cp.async pipeline stages (dense GEMM)
#define FBR 64          // flash-attn Q rows per CTA
#define FBC 64          // flash-attn KV cols per step

// ---------------- static scratch (allocation-free) ----------------
__device__ float  g_x   [BT*DD];                       // fp32 residual stream
__device__ __half g_h   [BT*DD];                       // LN output
__device__ __half g_qkv [BT*3*DD];
__device__ __half g_attn[BT*DD];
__device__ float  g_sa  [BT*DD];
__device__ __half g_ff1 [(size_t)BT*FFD];
__device__ __half g_vT  [(size_t)BB*HH*128*TT];        // V transposed, padded
// fp16 transposed weights
__device__ __half g_wqkvT [(size_t)LL*3*DD*DD];        // [l][n=3D][k=D]
__device__ __half g_wprojT[(size_t)LL*DD*DD];
__device__ __half g_w1T   [(size_t)LL*FFD*DD];
__device__ __half g_w2T   [(size_t)LL*DD*FFD];
__device__ __half g_wlmT  [(size_t)VV*DD];

// ---------------- helpers ----------------
__device__ __forceinline__ void mma_f16(float* c, const unsigned* a, const unsigned* b) {
    asm volatile(
        "mma.sync.aligned.m16n8k16.row.col.f32.f16.f16.f32 "
        "{%0,%1,%2,%3},{%4,%5,%6,%7},{%8,%9},{%0,%1,%2,%3};"
        : "+f"(c[0]), "+f"(c[1]), "+f"(c[2]), "+f"(c[3])
        : "r"(a[0]), "r"(a[1]), "r"(a[2]), "r"(a[3]), "r"(b[0]), "r"(b[1]));
}

__device__ __forceinline__ void ldsm4(unsigned& r0, unsigned& r1, unsigned& r2, unsigned& r3,
                                      unsigned addr) {
    asm volatile("ldmatrix.sync.aligned.m8n8.x4.shared.b16 {%0,%1,%2,%3}, [%4];"
                 : "=r"(r0), "=r"(r1), "=r"(r2), "=r"(r3) : "r"(addr));
}

// dense smem tile: 128 rows x 32 halfs (16 words/row). chunk = 16B.
__device__ __forceinline__ int sw_idx(int row, int chunk, int w) {
    return row * 16 + ((chunk ^ ((row >> 1) & 3)) << 2) + w;
}
// flash-attn smem tile: 64 rows x 64 halfs (128B/row), 8 chunks of 16B.
__device__ __forceinline__ int fsw(int row, int chunk) {
    return row * 128 + ((chunk ^ (row & 7)) << 4);
}

__device__ __forceinline__ void cp16(unsigned dst, const void* src) {
    asm volatile("cp.async.cg.shared.global [%0], [%1], 16;" :: "r"(dst), "l"(src));
}
__device__ __forceinline__ void cp_commit() { asm volatile("cp.async.commit_group;"); }
template<int N>
__device__ __forceinline__ void cp_wait() { asm volatile("cp.async.wait_group %0;" :: "n"(N)); }

// ---------------- embedding ----------------
__global__ void embed_kernel(const int* __restrict__ idx,
                             const float* __restrict__ tok,
                             const float* __restrict__ pos) {
    int bt = blockIdx.x;
    long long row = (long long)idx[bt];
    int t = bt % TT;
    const float* te = tok + row * DD;
    const float* pe = pos + (long long)t * DD;
    float* xo = g_x + (long long)bt * DD;
    for (int d = threadIdx.x; d < DD; d += blockDim.x)
        xo[d] = te[d] + pe[d];
}

// ---------------- fast transpose + cvt: fp32 [R][C] -> fp16 [C][R] --------
// 64(R) x 32(C) tiles, half2 coalesced writes. block (32,8).
__global__ void transpose_cvt2(const float* __restrict__ src, __half* __restrict__ dst,
                               int R, int C) {
    __shared__ float s[64][33];
    const float* sp = src + (size_t)blockIdx.z * R * C;
    __half* dp = dst + (size_t)blockIdx.z * R * C;
    int tx = threadIdx.x, ty = threadIdx.y;
    int r0 = blockIdx.y * 64, c0 = blockIdx.x * 32;
    #pragma unroll
    for (int i = 0; i < 8; i++) {
        int rl = ty + i * 8;
        s[rl][tx] = sp[(long long)(r0 + rl) * C + c0 + tx];
    }
    __syncthreads();
    #pragma unroll
    for (int i = 0; i < 4; i++) {
        int cl = ty + i * 8;
        __half2 v = __floats2half2_rn(s[2 * tx][cl], s[2 * tx + 1][cl]);
        *reinterpret_cast<__half2*>(dp + (long long)(c0 + cl) * R + r0 + 2 * tx) = v;
    }
}

// ---------------- pack wq/wk/wv -> transposed fp16 [L][3D][D] (fused) -----
// z = m*(LL*HH) + l*HH + h. Each handles [D][HD] -> [HD][D] slab.
// grid: x = HDD/32, y = DD/64.
__global__ void pack_qkv_all(const float* __restrict__ wq,
                             const float* __restrict__ wk,
                             const float* __restrict__ wv) {
    __shared__ float s[64][33];
    int z = blockIdx.z;
    int m = z / (LL * HH);
    int lh = z % (LL * HH);
    int l = lh / HH, h = lh % HH;
    const float* base = (m == 0) ? wq : ((m == 1) ? wk : wv);
    const float* sp = base + (long long)lh * DD * HDD;
    __half* dp = g_wqkvT + ((long long)(l * 3 + m) * DD + h * HDD) * DD;
    int tx = threadIdx.x, ty = threadIdx.y;
    int r0 = blockIdx.y * 64, c0 = blockIdx.x * 32;   // r: d, c: hd
    #pragma unroll
    for (int i = 0; i < 8; i++) {
        int rl = ty + i * 8;
        s[rl][tx] = sp[(long long)(r0 + rl) * HDD + c0 + tx];
    }
    __syncthreads();
    #pragma unroll
    for (int i = 0; i < 4; i++) {
        int cl = ty + i * 8;
        __half2 v = __floats2half2_rn(s[2 * tx][cl], s[2 * tx + 1][cl]);
        *reinterpret_cast<__half2*>(dp + (long long)(c0 + cl) * DD + r0 + 2 * tx) = v;
    }
}

// ---------------- V transpose per layer: qkv -> vT [bh][128(pad)][T] ------
__global__ void v_transpose() {
    __shared__ __half s[32][33];
    int z = blockIdx.z;                 // b*H + h
    int b = z / HH, h = z % HH;
    int t0 = blockIdx.x * 32;
    int d0 = blockIdx.y * 32;
    int tx = threadIdx.x, ty = threadIdx.y;
    const __half* v = g_qkv + (long long)b * TT * 3 * DD + 2 * DD + h * HDD;
    #pragma unroll
    for (int i = 0; i < 4; i++) {
        int t = t0 + ty + i * 8;
        s[ty + i * 8][tx] = v[(long long)t * 3 * DD + d0 + tx];
    }
    __syncthreads();
    __half* o = g_vT + (long long)z * 128 * TT;
    #pragma unroll
    for (int i = 0; i < 4; i++) {
        int d = d0 + ty + i * 8;
        o[(long long)d * TT + t0 + tx] = s[tx][ty + i * 8];
    }
}

// ---------------- layernorm (fp32 in, fp16 out) ----------------
__global__ void ln_kernel(const float* __restrict__ in,
                          const float* __restrict__ g,
                          const float* __restrict__ b,
                          __half* __restrict__ out) {
    int row = blockIdx.x;
    const float* x = in + (long long)row * DD;
    __shared__ float rs[256];
    __shared__ float rs2[256];
    float s = 0.f, s2 = 0.f;
    for (int d = threadIdx.x; d < DD; d += 256) {
        float v = x[d];
        s += v; s2 += v * v;
    }
    rs[threadIdx.x] = s; rs2[threadIdx.x] = s2;
    __syncthreads();
    for (int o = 128; o > 0; o >>= 1) {
        if (threadIdx.x < o) { rs[threadIdx.x] += rs[threadIdx.x + o]; rs2[threadIdx.x] += rs2[threadIdx.x + o]; }
        __syncthreads();
    }
    float mean = rs[0] * (1.0f / DD);
    float var  = rs2[0] * (1.0f / DD) - mean * mean;
    float rstd = rsqrtf(var + 1e-5f);
    __half* o = out + (long long)row * DD;
    for (int d = threadIdx.x; d < DD; d += 256)
        o[d] = __float2half((x[d] - mean) * rstd * g[d] + b[d]);
}

// ---------------- flash attention: Q@K^T -> online softmax -> @V ----------
// CTA: 64 Q rows of one (b,h). 4 warps x 16 rows. 2-stage cp.async KV.
// Single __syncthreads per step (next-stage issue AFTER the sync).
__global__ void __launch_bounds__(128, 2) flash_attn() {
    __shared__ __align__(16) __half Qs[FBR * 64];
    __shared__ __align__(16) __half Ks[2][FBC * 64];
    __shared__ __align__(16) __half Vs[2][64 * FBC];

    const int mt = (int)gridDim.x - 1 - (int)blockIdx.x;  // long CTAs first
    const int bmq = mt * FBR;
    const int z = blockIdx.y;                  // b*HH + h
    const int b = z / HH, h = z % HH;
    const int nsteps = mt + 1;

    const int tid  = threadIdx.x;
    const int warp = tid >> 5;
    const int lane = tid & 31;
    const int g    = lane >> 2;
    const int tig  = lane & 3;
    const int lm_i = lane >> 3;
    const int lm_r = lane & 7;
    const int wq0  = warp * 16;

    const __half* Qg = g_qkv + ((long long)b * TT + bmq) * 3 * DD + h * HDD;
    const __half* Kg = g_qkv + (long long)b * TT * 3 * DD + DD + h * HDD;
    const __half* Vg = g_vT + (long long)z * 128 * TT;

    const unsigned sQ = (unsigned)__cvta_generic_to_shared(Qs);
    const unsigned sK = (unsigned)__cvta_generic_to_shared(&Ks[0][0]);
    const unsigned sV = (unsigned)__cvta_generic_to_shared(&Vs[0][0]);

    auto loadKV = [&](int buf, int s0) {
        #pragma unroll
        for (int p = 0; p < 4; p++) {
            int i = p * 128 + tid;
            int row = i >> 3, ch = i & 7;
            cp16(sK + buf * 8192 + fsw(row, ch), Kg + (long long)(s0 + row) * 3 * DD + ch * 8);
        }
        #pragma unroll
        for (int p = 0; p < 4; p++) {
            int i = p * 128 + tid;
            int row = i >> 3, ch = i & 7;
            cp16(sV + buf * 8192 + fsw(row, ch), Vg + (long long)row * TT + s0 + ch * 8);
        }
        cp_commit();
    };

    // prologue: Q + KV0 in one group
    #pragma unroll
    for (int p = 0; p < 4; p++) {
        int i = p * 128 + tid;
        int row = i >> 3, ch = i & 7;
        cp16(sQ + fsw(row, ch), Qg + (long long)row * 3 * DD + ch * 8);
    }
    {
        #pragma unroll
        for (int p = 0; p < 4; p++) {
            int i = p * 128 + tid;
            int row = i >> 3, ch = i & 7;
            cp16(sK + fsw(row, ch), Kg + (long long)row * 3 * DD + ch * 8);
        }
        #pragma unroll
        for (int p = 0; p < 4; p++) {
            int i = p * 128 + tid;
            int row = i >> 3, ch = i & 7;
            cp16(sV + fsw(row, ch), Vg + (long long)row * TT + ch * 8);
        }
        cp_commit();
    }

    unsigned qf[4][4];
    float oacc[8][4];
    #pragma unroll
    for (int j = 0; j < 8; j++)
        #pragma unroll
        for (int q = 0; q < 4; q++) oacc[j][q] = 0.f;
    float m2[2] = {-1e30f, -1e30f};
    float l2[2] = {0.f, 0.f};
    const int t0 = bmq + wq0 + g;
    const int t1 = t0 + 8;

    for (int it = 0; it < nsteps; it++) {
        int buf = it & 1;
        cp_wait<0>();
        __syncthreads();
        if (it + 1 < nsteps) loadKV(buf ^ 1, (it + 1) * FBC);

        if (it == 0) {
            #pragma unroll
            for (int ks = 0; ks < 4; ks++) {
                int row = wq0 + (lm_i & 1) * 8 + lm_r;
                int ch  = ks * 2 + (lm_i >> 1);
                ldsm4(qf[ks][0], qf[ks][1], qf[ks][2], qf[ks][3], sQ + fsw(row, ch));
            }
        }

        // S = Q @ K^T
        float sacc[8][4];
        #pragma unroll
        for (int j = 0; j < 8; j++)
            #pragma unroll
            for (int q = 0; q < 4; q++) sacc[j][q] = 0.f;
        #pragma unroll
        for (int ks = 0; ks < 4; ks++) {
            #pragma unroll
            for (int njp = 0; njp < 4; njp++) {
                unsigned bb[4];
                int row = njp * 16 + (lm_i >> 1) * 8 + lm_r;
                int ch  = ks * 2 + (lm_i & 1);
                ldsm4(bb[0], bb[1], bb[2], bb[3], sK + buf * 8192 + fsw(row, ch));
                mma_f16(sacc[2 * njp],     qf[ks], bb);
                mma_f16(sacc[2 * njp + 1], qf[ks], bb + 2);
            }
        }

        // online softmax
        const bool last = (it == nsteps - 1);
        const int s0 = it * FBC;
        float mx0 = m2[0], mx1 = m2[1];
        #pragma unroll
        for (int nj = 0; nj < 8; nj++) {
            float v0 = sacc[nj][0] * 0.125f;
            float v1 = sacc[nj][1] * 0.125f;
            float v2 = sacc[nj][2] * 0.125f;
            float v3 = sacc[nj][3] * 0.125f;
            if (last) {
                int c0 = s0 + nj * 8 + 2 * tig, c1 = c0 + 1;
                if (c0 > t0) v0 = -1e30f;
                if (c1 > t0) v1 = -1e30f;
                if (c0 > t1) v2 = -1e30f;
                if (c1 > t1) v3 = -1e30f;
            }
            sacc[nj][0] = v0; sacc[nj][1] = v1; sacc[nj][2] = v2; sacc[nj][3] = v3;
            mx0 = fmaxf(mx0, fmaxf(v0, v1));
            mx1 = fmaxf(mx1, fmaxf(v2, v3));
        }
        mx0 = fmaxf(mx0, __shfl_xor_sync(0xffffffff, mx0, 1));
        mx0 = fmaxf(mx0, __shfl_xor_sync(0xffffffff, mx0, 2));
        mx1 = fmaxf(mx1, __shfl_xor_sync(0xffffffff, mx1, 1));
        mx1 = fmaxf(mx1, __shfl_xor_sync(0xffffffff, mx1, 2));
        float sc0 = __expf(m2[0] - mx0);
        float sc1 = __expf(m2[1] - mx1);
        m2[0] = mx0; m2[1] = mx1;
        float sum0 = 0.f, sum1 = 0.f;
        unsigned pf[8][2];
        #pragma unroll
        for (int nj = 0; nj < 8; nj++) {
            float p0 = __expf(sacc[nj][0] - mx0);
            float p1 = __expf(sacc[nj][1] - mx0);
            float p2 = __expf(sacc[nj][2] - mx1);
            float p3 = __expf(sacc[nj][3] - mx1);
            sum0 += p0 + p1; sum1 += p2 + p3;
            __half2 h0 = __floats2half2_rn(p0, p1);
            __half2 h1 = __floats2half2_rn(p2, p3);
            pf[nj][0] = *reinterpret_cast<unsigned*>(&h0);
            pf[nj][1] = *reinterpret_cast<unsigned*>(&h1);
        }
        sum0 += __shfl_xor_sync(0xffffffff, sum0, 1);
        sum0 += __shfl_xor_sync(0xffffffff, sum0, 2);
        sum1 += __shfl_xor_sync(0xffffffff, sum1, 1);
        sum1 += __shfl_xor_sync(0xffffffff, sum1, 2);
        l2[0] = l2[0] * sc0 + sum0;
        l2[1] = l2[1] * sc1 + sum1;
        #pragma unroll
        for (int nj = 0; nj < 8; nj++) {
            oacc[nj][0] *= sc0; oacc[nj][1] *= sc0;
            oacc[nj][2] *= sc1; oacc[nj][3] *= sc1;
        }

        // O += P @ V
        #pragma unroll
        for (int j = 0; j < 4; j++) {
            unsigned af[4] = {pf[2 * j][0], pf[2 * j][1], pf[2 * j + 1][0], pf[2 * j + 1][1]};
            #pragma unroll
            for (int njp = 0; njp < 4; njp++) {
                unsigned bb[4];
                int row = njp * 16 + (lm_i >> 1) * 8 + lm_r;
                int ch  = j * 2 + (lm_i & 1);
                ldsm4(bb[0], bb[1], bb[2], bb[3], sV + buf * 8192 + fsw(row, ch));
                mma_f16(oacc[2 * njp],     af, bb);
                mma_f16(oacc[2 * njp + 1], af, bb + 2);
            }
        }
    }

    float inv0 = 1.0f / l2[0];
    float inv1 = 1.0f / l2[1];
    __half* O0 = g_attn + ((long long)b * TT + t0) * DD + h * HDD;
    __half* O1 = g_attn + ((long long)b * TT + t1) * DD + h * HDD;
    #pragma unroll
    for (int nj = 0; nj < 8; nj++) {
        int col = nj * 8 + 2 * tig;
        __half2 h0 = __floats2half2_rn(oacc[nj][0] * inv0, oacc[nj][1] * inv0);
        __half2 h1 = __floats2half2_rn(oacc[nj][2] * inv1, oacc[nj][3] * inv1);
        *reinterpret_cast<__half2*>(O0 + col) = h0;
        *reinterpret_cast<__half2*>(O1 + col) = h1;
    }
}

// ---------------- fp16 tensor-core GEMM, 3-stage cp.async + LDSM ----------
// Single __syncthreads per K-iter (issue AFTER sync).
template<int EPI, bool OUTH>
__global__ void __launch_bounds__(128, 2)
mma_gemm(const __half* __restrict__ A, const __half* __restrict__ B,
         const float* __restrict__ bias, const float* __restrict__ aux,
         void* __restrict__ Cv,
         int M, int N, int K, int lda, int ldb, int ldc) {
    __shared__ __align__(16) unsigned As[NS][BM * 16];
    __shared__ __align__(16) unsigned Bs[NS][BN * 16];

    const int bm = blockIdx.x * BM;
    const int bn = blockIdx.y * BN;
    const int nIter = K / BK;

    const int tid  = threadIdx.x;
    const int warp = tid >> 5;
    const int lane = tid & 31;
    const int g    = lane >> 2;
    const int tig  = lane & 3;
    const int wm   = (warp & 1) * 64;
    const int wn   = (warp >> 1) * 64;

    const unsigned sA = (unsigned)__cvta_generic_to_shared(&As[0][0]);
    const unsigned sB = (unsigned)__cvta_generic_to_shared(&Bs[0][0]);

    const int lm_i = lane >> 3;
    const int lm_r = lane & 7;
    const int l_r = tid >> 2;
    const int l_c = tid & 3;

    auto issueLoads = [&](int stage, int k0) {
        #pragma unroll
        for (int p = 0; p < 4; p++) {
            int r = p * 32 + l_r;
            unsigned dst = sA + (unsigned)((stage * BM * 16 + sw_idx(r, l_c, 0)) * 4);
            cp16(dst, A + (long long)(bm + r) * lda + (k0 + l_c * 8));
        }
        #pragma unroll
        for (int p = 0; p < 4; p++) {
            int r = p * 32 + l_r;
            unsigned dst = sB + (unsigned)((stage * BN * 16 + sw_idx(r, l_c, 0)) * 4);
            cp16(dst, B + (long long)(bn + r) * ldb + (k0 + l_c * 8));
        }
        cp_commit();
    };

    float acc[4][8][4];
    #pragma unroll
    for (int i = 0; i < 4; i++)
        #pragma unroll
        for (int j = 0; j < 8; j++)
            #pragma unroll
            for (int q = 0; q < 4; q++) acc[i][j][q] = 0.f;

    issueLoads(0, 0);
    if (nIter > 1) issueLoads(1, BK);

    for (int it = 0; it < nIter; it++) {
        int buf = it % NS;
        if (it + 1 < nIter) cp_wait<1>();
        else                cp_wait<0>();
        __syncthreads();
        if (it + 2 < nIter) issueLoads((it + 2) % NS, (it + 2) * BK);

        #pragma unroll
        for (int ks = 0; ks < 2; ks++) {
            unsigned af[4][4];
            #pragma unroll
            for (int mi = 0; mi < 4; mi++) {
                int row = wm + mi * 16 + (lm_i & 1) * 8 + lm_r;
                int chunk = ks * 2 + (lm_i >> 1);
                unsigned addr = sA + (unsigned)((buf * BM * 16 + sw_idx(row, chunk, 0)) * 4);
                ldsm4(af[mi][0], af[mi][1], af[mi][2], af[mi][3], addr);
            }
            #pragma unroll
            for (int njp = 0; njp < 4; njp++) {
                unsigned bb[4];
                int row = wn + njp * 16 + (lm_i >> 1) * 8 + lm_r;
                int chunk = ks * 2 + (lm_i & 1);
                unsigned addr = sB + (unsigned)((buf * BN * 16 + sw_idx(row, chunk, 0)) * 4);
                ldsm4(bb[0], bb[1], bb[2], bb[3], addr);
                #pragma unroll
                for (int mi = 0; mi < 4; mi++) {
                    mma_f16(acc[mi][2 * njp],     af[mi], bb);
                    mma_f16(acc[mi][2 * njp + 1], af[mi], bb + 2);
                }
            }
        }
    }

    #pragma unroll
    for (int mi = 0; mi < 4; mi++) {
        int row = bm + wm + mi * 16 + g;
        #pragma unroll
        for (int nj = 0; nj < 8; nj++) {
            int col = bn + wn + nj * 8 + tig * 2;
            if (col >= N) continue;
            float v0 = acc[mi][nj][0];
            float v1 = acc[mi][nj][1];
            float v2 = acc[mi][nj][2];
            float v3 = acc[mi][nj][3];
            if (EPI >= 1) {
                float bb0 = bias[col];
                float bb1 = bias[col + 1];
                v0 += bb0; v1 += bb1; v2 += bb0; v3 += bb1;
            }
            if (EPI == 2) {
                v0 = fmaxf(v0, 0.f); v1 = fmaxf(v1, 0.f);
                v2 = fmaxf(v2, 0.f); v3 = fmaxf(v3, 0.f);
            }
            if (EPI == 3) {
                float2 a0 = *reinterpret_cast<const float2*>(aux + (long long)row * ldc + col);
                float2 a1 = *reinterpret_cast<const float2*>(aux + (long long)(row + 8) * ldc + col);
                v0 += a0.x; v1 += a0.y; v2 += a1.x; v3 += a1.y;
            }
            if (OUTH) {
                __half* C = (__half*)Cv;
                *reinterpret_cast<__half2*>(C + (long long)row * ldc + col) =
                    __floats2half2_rn(v0, v1);
                *reinterpret_cast<__half2*>(C + (long long)(row + 8) * ldc + col) =
                    __floats2half2_rn(v2, v3);
            } else {
                float* C = (float*)Cv;
                *reinterpret_cast<float2*>(C + (long long)row * ldc + col)       = make_float2(v0, v1);
                *reinterpret_cast<float2*>(C + (long long)(row + 8) * ldc + col) = make_float2(v2, v3);
            }
        }
    }
}

extern "C" void kernel_launch(void* const* d_in, const int* in_sizes, int n_in,
                              void* d_out, int out_size) {
    const int*   idx     = (const int*)d_in[0];
    const float* tok_emb = (const float*)d_in[1];
    const float* pos_emb = (const float*)d_in[2];
    const float* wq      = (const float*)d_in[3];
    const float* wk      = (const float*)d_in[4];
    const float* wv      = (const float*)d_in[5];
    const float* w_proj  = (const float*)d_in[6];
    const float* b_proj  = (const float*)d_in[7];
    const float* w1      = (const float*)d_in[8];
    const float* b1      = (const float*)d_in[9];
    const float* w2      = (const float*)d_in[10];
    const float* b2      = (const float*)d_in[11];
    const float* ln1_g   = (const float*)d_in[12];
    const float* ln1_b   = (const float*)d_in[13];
    const float* ln2_g   = (const float*)d_in[14];
    const float* ln2_b   = (const float*)d_in[15];
    const float* lnf_g   = (const float*)d_in[16];
    const float* lnf_b   = (const float*)d_in[17];
    const float* w_lm    = (const float*)d_in[18];
    const float* b_lm    = (const float*)d_in[19];
    float* out = (float*)d_out;

    float  *px, *psa;
    __half *ph, *pqkv, *pattn, *pff1;
    __half *pwqkvT, *pwprojT, *pw1T, *pw2T, *pwlmT;
    cudaGetSymbolAddress((void**)&px,      g_x);
    cudaGetSymbolAddress((void**)&ph,      g_h);
    cudaGetSymbolAddress((void**)&pqkv,    g_qkv);
    cudaGetSymbolAddress((void**)&pattn,   g_attn);
    cudaGetSymbolAddress((void**)&psa,     g_sa);
    cudaGetSymbolAddress((void**)&pff1,    g_ff1);
    cudaGetSymbolAddress((void**)&pwqkvT,  g_wqkvT);
    cudaGetSymbolAddress((void**)&pwprojT, g_wprojT);
    cudaGetSymbolAddress((void**)&pw1T,    g_w1T);
    cudaGetSymbolAddress((void**)&pw2T,    g_w2T);
    cudaGetSymbolAddress((void**)&pwlmT,   g_wlmT);

    // ---- weight prep: transpose + fp16 cvt (half2 writes, fused qkv) ----
    {
        dim3 th(32, 8);
        pack_qkv_all<<<dim3(HDD/32, DD/64, 3*LL*HH), th>>>(wq, wk, wv);
        transpose_cvt2<<<dim3(DD/32,  DD/64,  LL), th>>>(w_proj, pwprojT, DD,  DD);
        transpose_cvt2<<<dim3(FFD/32, DD/64,  LL), th>>>(w1,     pw1T,    DD,  FFD);
        transpose_cvt2<<<dim3(DD/32,  FFD/64, LL), th>>>(w2,     pw2T,    FFD, DD);
        transpose_cvt2<<<dim3(VV/32,  DD/64,  1),  th>>>(w_lm,   pwlmT,   DD,  VV);
    }
    embed_kernel<<<BT, 256>>>(idx, tok_emb, pos_emb);

    for (int l = 0; l < LL; l++) {
        ln_kernel<<<BT, 256>>>(px, ln1_g + (long long)l*DD, ln1_b + (long long)l*DD, ph);

        // qkv = h @ wqkvT^T  -> fp16
        mma_gemm<0,true><<<dim3(BT/BM, 3*DD/BN), 128>>>(
            ph, pwqkvT + (long long)l*3*DD*DD, nullptr, nullptr, pqkv,
            BT, 3*DD, DD, DD, DD, 3*DD);

        // vT per head
        v_transpose<<<dim3(TT/32, HDD/32, BB*HH), dim3(32, 8)>>>();

        // fused attention -> g_attn
        flash_attn<<<dim3(TT/FBR, BB*HH), 128>>>();

        // sa = attn @ w_proj + b_proj -> fp32
        mma_gemm<1,false><<<dim3(BT/BM, DD/BN), 128>>>(
            pattn, pwprojT + (long long)l*DD*DD, b_proj + (long long)l*DD, nullptr, psa,
            BT, DD, DD, DD, DD, DD);

        ln_kernel<<<BT, 256>>>(px, ln2_g + (long long)l*DD, ln2_b + (long long)l*DD, ph);

        // ff1 = relu(h @ w1 + b1) -> fp16
        mma_gemm<2,true><<<dim3(BT/BM, FFD/BN), 128>>>(
            ph, pw1T + (long long)l*FFD*DD, b1 + (long long)l*FFD, nullptr, pff1,
            BT, FFD, DD, DD, DD, FFD);

        // x = ff1 @ w2 + b2 + sa  (residual fused) -> fp32
        mma_gemm<3,false><<<dim3(BT/BM, DD/BN), 128>>>(
            pff1, pw2T + (long long)l*DD*FFD, b2 + (long long)l*DD, psa, px,
            BT, DD, FFD, FFD, FFD, DD);
    }

    ln_kernel<<<BT, 256>>>(px, lnf_g, lnf_b, ph);

    // logits = h @ w_lm + b_lm -> fp32
    mma_gemm<1,false><<<dim3(BT/BM, VV/BN), 128>>>(
        ph, pwlmT, b_lm, nullptr, out,
        BT, VV, DD, DD, DD, VV);
}

// round 14
// speedup vs baseline: 1.0872x; 1.0872x over previous
#include <cuda_runtime.h>
#include <cuda_fp16.h>
#include <math.h>

// Problem constants
#define BB  2
#define TT  1024
#define DD  1024
#define HH  16
#define HDD 64
#define LL  3
#define VV  32000
#define FFD 4096
#define BT  (BB*TT)

#define BM 128
#define BN 128
#define BK 32
#define NS 3            // cp.async pipeline stages (dense GEMM)
#define FBR 64          // flash-attn Q rows per CTA
#define FBC 64          // flash-attn KV cols per step

// ---------------- static scratch (allocation-free) ----------------
__device__ float  g_x   [BT*DD];                       // fp32 residual stream
__device__ __half g_h   [BT*DD];                       // LN output
__device__ __half g_qkv [BT*3*DD];
__device__ __half g_attn[BT*DD];
__device__ float  g_sa  [BT*DD];
__device__ __half g_ff1 [(size_t)BT*FFD];
__device__ __half g_vT  [(size_t)BB*HH*128*TT];        // V transposed, padded
// fp16 transposed weights
__device__ __half g_wqkvT [(size_t)LL*3*DD*DD];        // [l][n=3D][k=D]
__device__ __half g_wprojT[(size_t)LL*DD*DD];
__device__ __half g_w1T   [(size_t)LL*FFD*DD];
__device__ __half g_w2T   [(size_t)LL*DD*FFD];
__device__ __half g_wlmT  [(size_t)VV*DD];

// ---------------- helpers ----------------
__device__ __forceinline__ void mma_f16(float* c, const unsigned* a, const unsigned* b) {
    asm volatile(
        "mma.sync.aligned.m16n8k16.row.col.f32.f16.f16.f32 "
        "{%0,%1,%2,%3},{%4,%5,%6,%7},{%8,%9},{%0,%1,%2,%3};"
        : "+f"(c[0]), "+f"(c[1]), "+f"(c[2]), "+f"(c[3])
        : "r"(a[0]), "r"(a[1]), "r"(a[2]), "r"(a[3]), "r"(b[0]), "r"(b[1]));
}

__device__ __forceinline__ void ldsm4(unsigned& r0, unsigned& r1, unsigned& r2, unsigned& r3,
                                      unsigned addr) {
    asm volatile("ldmatrix.sync.aligned.m8n8.x4.shared.b16 {%0,%1,%2,%3}, [%4];"
                 : "=r"(r0), "=r"(r1), "=r"(r2), "=r"(r3) : "r"(addr));
}

// dense smem tile: 128 rows x 32 halfs (16 words/row). chunk = 16B.
__device__ __forceinline__ int sw_idx(int row, int chunk, int w) {
    return row * 16 + ((chunk ^ ((row >> 1) & 3)) << 2) + w;
}
// flash-attn smem tile: 64 rows x 64 halfs (128B/row), 8 chunks of 16B.
__device__ __forceinline__ int fsw(int row, int chunk) {
    return row * 128 + ((chunk ^ (row & 7)) << 4);
}

__device__ __forceinline__ void cp16(unsigned dst, const void* src) {
    asm volatile("cp.async.cg.shared.global [%0], [%1], 16;" :: "r"(dst), "l"(src));
}
__device__ __forceinline__ void cp_commit() { asm volatile("cp.async.commit_group;"); }
template<int N>
__device__ __forceinline__ void cp_wait() { asm volatile("cp.async.wait_group %0;" :: "n"(N)); }

// ---------------- embedding ----------------
__global__ void embed_kernel(const int* __restrict__ idx,
                             const float* __restrict__ tok,
                             const float* __restrict__ pos) {
    int bt = blockIdx.x;
    long long row = (long long)idx[bt];
    int t = bt % TT;
    const float* te = tok + row * DD;
    const float* pe = pos + (long long)t * DD;
    float* xo = g_x + (long long)bt * DD;
    for (int d = threadIdx.x; d < DD; d += blockDim.x)
        xo[d] = te[d] + pe[d];
}

// ---------------- fast transpose + cvt: fp32 [R][C] -> fp16 [C][R] --------
// 64(R) x 32(C) tiles, half2 coalesced writes. block (32,8).
__global__ void transpose_cvt2(const float* __restrict__ src, __half* __restrict__ dst,
                               int R, int C) {
    __shared__ float s[64][33];
    const float* sp = src + (size_t)blockIdx.z * R * C;
    __half* dp = dst + (size_t)blockIdx.z * R * C;
    int tx = threadIdx.x, ty = threadIdx.y;
    int r0 = blockIdx.y * 64, c0 = blockIdx.x * 32;
    #pragma unroll
    for (int i = 0; i < 8; i++) {
        int rl = ty + i * 8;
        s[rl][tx] = sp[(long long)(r0 + rl) * C + c0 + tx];
    }
    __syncthreads();
    #pragma unroll
    for (int i = 0; i < 4; i++) {
        int cl = ty + i * 8;
        __half2 v = __floats2half2_rn(s[2 * tx][cl], s[2 * tx + 1][cl]);
        *reinterpret_cast<__half2*>(dp + (long long)(c0 + cl) * R + r0 + 2 * tx) = v;
    }
}

// ---------------- pack wq/wk/wv -> transposed fp16 [L][3D][D] (fused) -----
// z = m*(LL*HH) + l*HH + h. grid: x = HDD/32, y = DD/64.
__global__ void pack_qkv_all(const float* __restrict__ wq,
                             const float* __restrict__ wk,
                             const float* __restrict__ wv) {
    __shared__ float s[64][33];
    int z = blockIdx.z;
    int m = z / (LL * HH);
    int lh = z % (LL * HH);
    int l = lh / HH, h = lh % HH;
    const float* base = (m == 0) ? wq : ((m == 1) ? wk : wv);
    const float* sp = base + (long long)lh * DD * HDD;
    __half* dp = g_wqkvT + ((long long)(l * 3 + m) * DD + h * HDD) * DD;
    int tx = threadIdx.x, ty = threadIdx.y;
    int r0 = blockIdx.y * 64, c0 = blockIdx.x * 32;   // r: d, c: hd
    #pragma unroll
    for (int i = 0; i < 8; i++) {
        int rl = ty + i * 8;
        s[rl][tx] = sp[(long long)(r0 + rl) * HDD + c0 + tx];
    }
    __syncthreads();
    #pragma unroll
    for (int i = 0; i < 4; i++) {
        int cl = ty + i * 8;
        __half2 v = __floats2half2_rn(s[2 * tx][cl], s[2 * tx + 1][cl]);
        *reinterpret_cast<__half2*>(dp + (long long)(c0 + cl) * DD + r0 + 2 * tx) = v;
    }
}

// ---------------- V transpose per layer: qkv -> vT [bh][128(pad)][T] ------
__global__ void v_transpose() {
    __shared__ __half s[32][33];
    int z = blockIdx.z;                 // b*H + h
    int b = z / HH, h = z % HH;
    int t0 = blockIdx.x * 32;
    int d0 = blockIdx.y * 32;
    int tx = threadIdx.x, ty = threadIdx.y;
    const __half* v = g_qkv + (long long)b * TT * 3 * DD + 2 * DD + h * HDD;
    #pragma unroll
    for (int i = 0; i < 4; i++) {
        int t = t0 + ty + i * 8;
        s[ty + i * 8][tx] = v[(long long)t * 3 * DD + d0 + tx];
    }
    __syncthreads();
    __half* o = g_vT + (long long)z * 128 * TT;
    #pragma unroll
    for (int i = 0; i < 4; i++) {
        int d = d0 + ty + i * 8;
        o[(long long)d * TT + t0 + tx] = s[tx][ty + i * 8];
    }
}

// ---------------- layernorm (fp32 in, fp16 out) ----------------
__global__ void ln_kernel(const float* __restrict__ in,
                          const float* __restrict__ g,
                          const float* __restrict__ b,
                          __half* __restrict__ out) {
    int row = blockIdx.x;
    const float* x = in + (long long)row * DD;
    __shared__ float rs[256];
    __shared__ float rs2[256];
    float s = 0.f, s2 = 0.f;
    for (int d = threadIdx.x; d < DD; d += 256) {
        float v = x[d];
        s += v; s2 += v * v;
    }
    rs[threadIdx.x] = s; rs2[threadIdx.x] = s2;
    __syncthreads();
    for (int o = 128; o > 0; o >>= 1) {
        if (threadIdx.x < o) { rs[threadIdx.x] += rs[threadIdx.x + o]; rs2[threadIdx.x] += rs2[threadIdx.x + o]; }
        __syncthreads();
    }
    float mean = rs[0] * (1.0f / DD);
    float var  = rs2[0] * (1.0f / DD) - mean * mean;
    float rstd = rsqrtf(var + 1e-5f);
    __half* o = out + (long long)row * DD;
    for (int d = threadIdx.x; d < DD; d += 256)
        o[d] = __float2half((x[d] - mean) * rstd * g[d] + b[d]);
}

// ---------------- flash attention (round-12 proven loop structure) --------
__global__ void __launch_bounds__(128, 2) flash_attn() {
    __shared__ __align__(16) __half Qs[FBR * 64];
    __shared__ __align__(16) __half Ks[2][FBC * 64];
    __shared__ __align__(16) __half Vs[2][64 * FBC];

    const int mt = (int)gridDim.x - 1 - (int)blockIdx.x;  // long CTAs first
    const int bmq = mt * FBR;
    const int z = blockIdx.y;                  // b*HH + h
    const int b = z / HH, h = z % HH;
    const int nsteps = mt + 1;

    const int tid  = threadIdx.x;
    const int warp = tid >> 5;
    const int lane = tid & 31;
    const int g    = lane >> 2;
    const int tig  = lane & 3;
    const int lm_i = lane >> 3;
    const int lm_r = lane & 7;
    const int wq0  = warp * 16;

    const __half* Qg = g_qkv + ((long long)b * TT + bmq) * 3 * DD + h * HDD;
    const __half* Kg = g_qkv + (long long)b * TT * 3 * DD + DD + h * HDD;
    const __half* Vg = g_vT + (long long)z * 128 * TT;

    const unsigned sQ = (unsigned)__cvta_generic_to_shared(Qs);
    const unsigned sK = (unsigned)__cvta_generic_to_shared(&Ks[0][0]);
    const unsigned sV = (unsigned)__cvta_generic_to_shared(&Vs[0][0]);

    // load Q tile (group 0)
    #pragma unroll
    for (int p = 0; p < 4; p++) {
        int i = p * 128 + tid;
        int row = i >> 3, ch = i & 7;
        cp16(sQ + fsw(row, ch), Qg + (long long)row * 3 * DD + ch * 8);
    }
    cp_commit();

    auto loadKV = [&](int buf, int s0) {
        #pragma unroll
        for (int p = 0; p < 4; p++) {
            int i = p * 128 + tid;
            int row = i >> 3, ch = i & 7;
            cp16(sK + buf * 8192 + fsw(row, ch), Kg + (long long)(s0 + row) * 3 * DD + ch * 8);
        }
        #pragma unroll
        for (int p = 0; p < 4; p++) {
            int i = p * 128 + tid;
            int row = i >> 3, ch = i & 7;
            cp16(sV + buf * 8192 + fsw(row, ch), Vg + (long long)row * TT + s0 + ch * 8);
        }
        cp_commit();
    };

    loadKV(0, 0);

    unsigned qf[4][4];
    float oacc[8][4];
    #pragma unroll
    for (int j = 0; j < 8; j++)
        #pragma unroll
        for (int q = 0; q < 4; q++) oacc[j][q] = 0.f;
    float m2[2] = {-1e30f, -1e30f};
    float l2[2] = {0.f, 0.f};
    const int t0 = bmq + wq0 + g;
    const int t1 = t0 + 8;

    for (int it = 0; it < nsteps; it++) {
        int buf = it & 1;
        if (it + 1 < nsteps) { loadKV(buf ^ 1, (it + 1) * FBC); cp_wait<1>(); }
        else                 { cp_wait<0>(); }
        __syncthreads();

        if (it == 0) {
            #pragma unroll
            for (int ks = 0; ks < 4; ks++) {
                int row = wq0 + (lm_i & 1) * 8 + lm_r;
                int ch  = ks * 2 + (lm_i >> 1);
                ldsm4(qf[ks][0], qf[ks][1], qf[ks][2], qf[ks][3], sQ + fsw(row, ch));
            }
        }

        // S = Q @ K^T
        float sacc[8][4];
        #pragma unroll
        for (int j = 0; j < 8; j++)
            #pragma unroll
            for (int q = 0; q < 4; q++) sacc[j][q] = 0.f;
        #pragma unroll
        for (int ks = 0; ks < 4; ks++) {
            #pragma unroll
            for (int njp = 0; njp < 4; njp++) {
                unsigned bb[4];
                int row = njp * 16 + (lm_i >> 1) * 8 + lm_r;
                int ch  = ks * 2 + (lm_i & 1);
                ldsm4(bb[0], bb[1], bb[2], bb[3], sK + buf * 8192 + fsw(row, ch));
                mma_f16(sacc[2 * njp],     qf[ks], bb);
                mma_f16(sacc[2 * njp + 1], qf[ks], bb + 2);
            }
        }

        // online softmax
        const bool last = (it == nsteps - 1);
        const int s0 = it * FBC;
        float mx0 = m2[0], mx1 = m2[1];
        #pragma unroll
        for (int nj = 0; nj < 8; nj++) {
            float v0 = sacc[nj][0] * 0.125f;
            float v1 = sacc[nj][1] * 0.125f;
            float v2 = sacc[nj][2] * 0.125f;
            float v3 = sacc[nj][3] * 0.125f;
            if (last) {
                int c0 = s0 + nj * 8 + 2 * tig, c1 = c0 + 1;
                if (c0 > t0) v0 = -1e30f;
                if (c1 > t0) v1 = -1e30f;
                if (c0 > t1) v2 = -1e30f;
                if (c1 > t1) v3 = -1e30f;
            }
            sacc[nj][0] = v0; sacc[nj][1] = v1; sacc[nj][2] = v2; sacc[nj][3] = v3;
            mx0 = fmaxf(mx0, fmaxf(v0, v1));
            mx1 = fmaxf(mx1, fmaxf(v2, v3));
        }
        mx0 = fmaxf(mx0, __shfl_xor_sync(0xffffffff, mx0, 1));
        mx0 = fmaxf(mx0, __shfl_xor_sync(0xffffffff, mx0, 2));
        mx1 = fmaxf(mx1, __shfl_xor_sync(0xffffffff, mx1, 1));
        mx1 = fmaxf(mx1, __shfl_xor_sync(0xffffffff, mx1, 2));
        float sc0 = __expf(m2[0] - mx0);
        float sc1 = __expf(m2[1] - mx1);
        m2[0] = mx0; m2[1] = mx1;
        float sum0 = 0.f, sum1 = 0.f;
        unsigned pf[8][2];
        #pragma unroll
        for (int nj = 0; nj < 8; nj++) {
            float p0 = __expf(sacc[nj][0] - mx0);
            float p1 = __expf(sacc[nj][1] - mx0);
            float p2 = __expf(sacc[nj][2] - mx1);
            float p3 = __expf(sacc[nj][3] - mx1);
            sum0 += p0 + p1; sum1 += p2 + p3;
            __half2 h0 = __floats2half2_rn(p0, p1);
            __half2 h1 = __floats2half2_rn(p2, p3);
            pf[nj][0] = *reinterpret_cast<unsigned*>(&h0);
            pf[nj][1] = *reinterpret_cast<unsigned*>(&h1);
        }
        sum0 += __shfl_xor_sync(0xffffffff, sum0, 1);
        sum0 += __shfl_xor_sync(0xffffffff, sum0, 2);
        sum1 += __shfl_xor_sync(0xffffffff, sum1, 1);
        sum1 += __shfl_xor_sync(0xffffffff, sum1, 2);
        l2[0] = l2[0] * sc0 + sum0;
        l2[1] = l2[1] * sc1 + sum1;
        #pragma unroll
        for (int nj = 0; nj < 8; nj++) {
            oacc[nj][0] *= sc0; oacc[nj][1] *= sc0;
            oacc[nj][2] *= sc1; oacc[nj][3] *= sc1;
        }

        // O += P @ V
        #pragma unroll
        for (int j = 0; j < 4; j++) {
            unsigned af[4] = {pf[2 * j][0], pf[2 * j][1], pf[2 * j + 1][0], pf[2 * j + 1][1]};
            #pragma unroll
            for (int njp = 0; njp < 4; njp++) {
                unsigned bb[4];
                int row = njp * 16 + (lm_i >> 1) * 8 + lm_r;
                int ch  = j * 2 + (lm_i & 1);
                ldsm4(bb[0], bb[1], bb[2], bb[3], sV + buf * 8192 + fsw(row, ch));
                mma_f16(oacc[2 * njp],     af, bb);
                mma_f16(oacc[2 * njp + 1], af, bb + 2);
            }
        }
        __syncthreads();
    }

    float inv0 = 1.0f / l2[0];
    float inv1 = 1.0f / l2[1];
    __half* O0 = g_attn + ((long long)b * TT + t0) * DD + h * HDD;
    __half* O1 = g_attn + ((long long)b * TT + t1) * DD + h * HDD;
    #pragma unroll
    for (int nj = 0; nj < 8; nj++) {
        int col = nj * 8 + 2 * tig;
        __half2 h0 = __floats2half2_rn(oacc[nj][0] * inv0, oacc[nj][1] * inv0);
        __half2 h1 = __floats2half2_rn(oacc[nj][2] * inv1, oacc[nj][3] * inv1);
        *reinterpret_cast<__half2*>(O0 + col) = h0;
        *reinterpret_cast<__half2*>(O1 + col) = h1;
    }
}

// ---------------- fp16 tensor-core GEMM (round-12 proven loop) ------------
template<int EPI, bool OUTH>
__global__ void __launch_bounds__(128, 2)
mma_gemm(const __half* __restrict__ A, const __half* __restrict__ B,
         const float* __restrict__ bias, const float* __restrict__ aux,
         void* __restrict__ Cv,
         int M, int N, int K, int lda, int ldb, int ldc) {
    __shared__ __align__(16) unsigned As[NS][BM * 16];
    __shared__ __align__(16) unsigned Bs[NS][BN * 16];

    const int bm = blockIdx.x * BM;
    const int bn = blockIdx.y * BN;
    const int nIter = K / BK;

    const int tid  = threadIdx.x;
    const int warp = tid >> 5;
    const int lane = tid & 31;
    const int g    = lane >> 2;
    const int tig  = lane & 3;
    const int wm   = (warp & 1) * 64;
    const int wn   = (warp >> 1) * 64;

    const unsigned sA = (unsigned)__cvta_generic_to_shared(&As[0][0]);
    const unsigned sB = (unsigned)__cvta_generic_to_shared(&Bs[0][0]);

    const int lm_i = lane >> 3;
    const int lm_r = lane & 7;
    const int l_r = tid >> 2;
    const int l_c = tid & 3;

    auto issueLoads = [&](int stage, int k0) {
        #pragma unroll
        for (int p = 0; p < 4; p++) {
            int r = p * 32 + l_r;
            unsigned dst = sA + (unsigned)((stage * BM * 16 + sw_idx(r, l_c, 0)) * 4);
            cp16(dst, A + (long long)(bm + r) * lda + (k0 + l_c * 8));
        }
        #pragma unroll
        for (int p = 0; p < 4; p++) {
            int r = p * 32 + l_r;
            unsigned dst = sB + (unsigned)((stage * BN * 16 + sw_idx(r, l_c, 0)) * 4);
            cp16(dst, B + (long long)(bn + r) * ldb + (k0 + l_c * 8));
        }
    };

    float acc[4][8][4];
    #pragma unroll
    for (int i = 0; i < 4; i++)
        #pragma unroll
        for (int j = 0; j < 8; j++)
            #pragma unroll
            for (int q = 0; q < 4; q++) acc[i][j][q] = 0.f;

    issueLoads(0, 0);
    cp_commit();
    if (nIter > 1) { issueLoads(1, BK); cp_commit(); }

    for (int it = 0; it < nIter; it++) {
        int buf = it % NS;
        if (it + 2 < nIter) {
            issueLoads((it + 2) % NS, (it + 2) * BK);
            cp_commit();
            cp_wait<2>();
        } else if (it + 1 < nIter) {
            cp_wait<1>();
        } else {
            cp_wait<0>();
        }
        __syncthreads();

        #pragma unroll
        for (int ks = 0; ks < 2; ks++) {
            unsigned af[4][4];
            #pragma unroll
            for (int mi = 0; mi < 4; mi++) {
                int row = wm + mi * 16 + (lm_i & 1) * 8 + lm_r;
                int chunk = ks * 2 + (lm_i >> 1);
                unsigned addr = sA + (unsigned)((buf * BM * 16 + sw_idx(row, chunk, 0)) * 4);
                ldsm4(af[mi][0], af[mi][1], af[mi][2], af[mi][3], addr);
            }
            #pragma unroll
            for (int njp = 0; njp < 4; njp++) {
                unsigned bb[4];
                int row = wn + njp * 16 + (lm_i >> 1) * 8 + lm_r;
                int chunk = ks * 2 + (lm_i & 1);
                unsigned addr = sB + (unsigned)((buf * BN * 16 + sw_idx(row, chunk, 0)) * 4);
                ldsm4(bb[0], bb[1], bb[2], bb[3], addr);
                #pragma unroll
                for (int mi = 0; mi < 4; mi++) {
                    mma_f16(acc[mi][2 * njp],     af[mi], bb);
                    mma_f16(acc[mi][2 * njp + 1], af[mi], bb + 2);
                }
            }
        }
        __syncthreads();
    }

    #pragma unroll
    for (int mi = 0; mi < 4; mi++) {
        int row = bm + wm + mi * 16 + g;
        #pragma unroll
        for (int nj = 0; nj < 8; nj++) {
            int col = bn + wn + nj * 8 + tig * 2;
            if (col >= N) continue;
            float v0 = acc[mi][nj][0];
            float v1 = acc[mi][nj][1];
            float v2 = acc[mi][nj][2];
            float v3 = acc[mi][nj][3];
            if (EPI >= 1) {
                float bb0 = bias[col];
                float bb1 = bias[col + 1];
                v0 += bb0; v1 += bb1; v2 += bb0; v3 += bb1;
            }
            if (EPI == 2) {
                v0 = fmaxf(v0, 0.f); v1 = fmaxf(v1, 0.f);
                v2 = fmaxf(v2, 0.f); v3 = fmaxf(v3, 0.f);
            }
            if (EPI == 3) {
                float2 a0 = *reinterpret_cast<const float2*>(aux + (long long)row * ldc + col);
                float2 a1 = *reinterpret_cast<const float2*>(aux + (long long)(row + 8) * ldc + col);
                v0 += a0.x; v1 += a0.y; v2 += a1.x; v3 += a1.y;
            }
            if (OUTH) {
                __half* C = (__half*)Cv;
                *reinterpret_cast<__half2*>(C + (long long)row * ldc + col) =
                    __floats2half2_rn(v0, v1);
                *reinterpret_cast<__half2*>(C + (long long)(row + 8) * ldc + col) =
                    __floats2half2_rn(v2, v3);
            } else {
                float* C = (float*)Cv;
                *reinterpret_cast<float2*>(C + (long long)row * ldc + col)       = make_float2(v0, v1);
                *reinterpret_cast<float2*>(C + (long long)(row + 8) * ldc + col) = make_float2(v2, v3);
            }
        }
    }
}

extern "C" void kernel_launch(void* const* d_in, const int* in_sizes, int n_in,
                              void* d_out, int out_size) {
    const int*   idx     = (const int*)d_in[0];
    const float* tok_emb = (const float*)d_in[1];
    const float* pos_emb = (const float*)d_in[2];
    const float* wq      = (const float*)d_in[3];
    const float* wk      = (const float*)d_in[4];
    const float* wv      = (const float*)d_in[5];
    const float* w_proj  = (const float*)d_in[6];
    const float* b_proj  = (const float*)d_in[7];
    const float* w1      = (const float*)d_in[8];
    const float* b1      = (const float*)d_in[9];
    const float* w2      = (const float*)d_in[10];
    const float* b2      = (const float*)d_in[11];
    const float* ln1_g   = (const float*)d_in[12];
    const float* ln1_b   = (const float*)d_in[13];
    const float* ln2_g   = (const float*)d_in[14];
    const float* ln2_b   = (const float*)d_in[15];
    const float* lnf_g   = (const float*)d_in[16];
    const float* lnf_b   = (const float*)d_in[17];
    const float* w_lm    = (const float*)d_in[18];
    const float* b_lm    = (const float*)d_in[19];
    float* out = (float*)d_out;

    float  *px, *psa;
    __half *ph, *pqkv, *pattn, *pff1;
    __half *pwqkvT, *pwprojT, *pw1T, *pw2T, *pwlmT;
    cudaGetSymbolAddress((void**)&px,      g_x);
    cudaGetSymbolAddress((void**)&ph,      g_h);
    cudaGetSymbolAddress((void**)&pqkv,    g_qkv);
    cudaGetSymbolAddress((void**)&pattn,   g_attn);
    cudaGetSymbolAddress((void**)&psa,     g_sa);
    cudaGetSymbolAddress((void**)&pff1,    g_ff1);
    cudaGetSymbolAddress((void**)&pwqkvT,  g_wqkvT);
    cudaGetSymbolAddress((void**)&pwprojT, g_wprojT);
    cudaGetSymbolAddress((void**)&pw1T,    g_w1T);
    cudaGetSymbolAddress((void**)&pw2T,    g_w2T);
    cudaGetSymbolAddress((void**)&pwlmT,   g_wlmT);

    // ---- weight prep: transpose + fp16 cvt (half2 writes, fused qkv) ----
    {
        dim3 th(32, 8);
        pack_qkv_all<<<dim3(HDD/32, DD/64, 3*LL*HH), th>>>(wq, wk, wv);
        transpose_cvt2<<<dim3(DD/32,  DD/64,  LL), th>>>(w_proj, pwprojT, DD,  DD);
        transpose_cvt2<<<dim3(FFD/32, DD/64,  LL), th>>>(w1,     pw1T,    DD,  FFD);
        transpose_cvt2<<<dim3(DD/32,  FFD/64, LL), th>>>(w2,     pw2T,    FFD, DD);
        transpose_cvt2<<<dim3(VV/32,  DD/64,  1),  th>>>(w_lm,   pwlmT,   DD,  VV);
    }
    embed_kernel<<<BT, 256>>>(idx, tok_emb, pos_emb);

    for (int l = 0; l < LL; l++) {
        ln_kernel<<<BT, 256>>>(px, ln1_g + (long long)l*DD, ln1_b + (long long)l*DD, ph);

        // qkv = h @ wqkvT^T  -> fp16
        mma_gemm<0,true><<<dim3(BT/BM, 3*DD/BN), 128>>>(
            ph, pwqkvT + (long long)l*3*DD*DD, nullptr, nullptr, pqkv,
            BT, 3*DD, DD, DD, DD, 3*DD);

        // vT per head
        v_transpose<<<dim3(TT/32, HDD/32, BB*HH), dim3(32, 8)>>>();

        // fused attention -> g_attn
        flash_attn<<<dim3(TT/FBR, BB*HH), 128>>>();

        // sa = attn @ w_proj + b_proj -> fp32
        mma_gemm<1,false><<<dim3(BT/BM, DD/BN), 128>>>(
            pattn, pwprojT + (long long)l*DD*DD, b_proj + (long long)l*DD, nullptr, psa,
            BT, DD, DD, DD, DD, DD);

        ln_kernel<<<BT, 256>>>(px, ln2_g + (long long)l*DD, ln2_b + (long long)l*DD, ph);

        // ff1 = relu(h @ w1 + b1) -> fp16
        mma_gemm<2,true><<<dim3(BT/BM, FFD/BN), 128>>>(
            ph, pw1T + (long long)l*FFD*DD, b1 + (long long)l*FFD, nullptr, pff1,
            BT, FFD, DD, DD, DD, FFD);

        // x = ff1 @ w2 + b2 + sa  (residual fused) -> fp32
        mma_gemm<3,false><<<dim3(BT/BM, DD/BN), 128>>>(
            pff1, pw2T + (long long)l*DD*FFD, b2 + (long long)l*DD, psa, px,
            BT, DD, FFD, FFD, FFD, DD);
    }

    ln_kernel<<<BT, 256>>>(px, lnf_g, lnf_b, ph);

    // logits = h @ w_lm + b_lm -> fp32
    mma_gemm<1,false><<<dim3(BT/BM, VV/BN), 128>>>(
        ph, pwlmT, b_lm, nullptr, out,
        BT, VV, DD, DD, DD, VV);
}

// round 15
// speedup vs baseline: 1.1582x; 1.0652x over previous
#include <cuda_runtime.h>
#include <cuda_fp16.h>
#include <math.h>

// Problem constants
#define BB  2
#define TT  1024
#define DD  1024
#define HH  16
#define HDD 64
#define LL  3
#define VV  32000
#define FFD 4096
#define BT  (BB*TT)

#define BM 128
#define BK 32
#define NS 3            // cp.async pipeline stages (dense GEMM)
#define FBR 64          // flash-attn Q rows per CTA
#define FBC 64          // flash-attn KV cols per step

// ---------------- static scratch (allocation-free) ----------------
__device__ float  g_x   [BT*DD];                       // fp32 residual stream
__device__ __half g_h   [BT*DD];                       // LN output
__device__ __half g_qkv [BT*3*DD];
__device__ __half g_attn[BT*DD];
__device__ float  g_sa  [BT*DD];
__device__ __half g_ff1 [(size_t)BT*FFD];
__device__ __half g_vT  [(size_t)BB*HH*128*TT];        // V transposed, padded
// fp16 transposed weights
__device__ __half g_wqkvT [(size_t)LL*3*DD*DD];        // [l][n=3D][k=D]
__device__ __half g_wprojT[(size_t)LL*DD*DD];
__device__ __half g_w1T   [(size_t)LL*FFD*DD];
__device__ __half g_w2T   [(size_t)LL*DD*FFD];
__device__ __half g_wlmT  [(size_t)VV*DD];

// ---------------- helpers ----------------
__device__ __forceinline__ void mma_f16(float* c, const unsigned* a, const unsigned* b) {
    asm volatile(
        "mma.sync.aligned.m16n8k16.row.col.f32.f16.f16.f32 "
        "{%0,%1,%2,%3},{%4,%5,%6,%7},{%8,%9},{%0,%1,%2,%3};"
        : "+f"(c[0]), "+f"(c[1]), "+f"(c[2]), "+f"(c[3])
        : "r"(a[0]), "r"(a[1]), "r"(a[2]), "r"(a[3]), "r"(b[0]), "r"(b[1]));
}

__device__ __forceinline__ void ldsm4(unsigned& r0, unsigned& r1, unsigned& r2, unsigned& r3,
                                      unsigned addr) {
    asm volatile("ldmatrix.sync.aligned.m8n8.x4.shared.b16 {%0,%1,%2,%3}, [%4];"
                 : "=r"(r0), "=r"(r1), "=r"(r2), "=r"(r3) : "r"(addr));
}

// dense smem tile: rows x 32 halfs (16 words/row). chunk = 16B.
__device__ __forceinline__ int sw_idx(int row, int chunk, int w) {
    return row * 16 + ((chunk ^ ((row >> 1) & 3)) << 2) + w;
}
// flash-attn smem tile: 64 rows x 64 halfs (128B/row), 8 chunks of 16B.
__device__ __forceinline__ int fsw(int row, int chunk) {
    return row * 128 + ((chunk ^ (row & 7)) << 4);
}

__device__ __forceinline__ void cp16(unsigned dst, const void* src) {
    asm volatile("cp.async.cg.shared.global [%0], [%1], 16;" :: "r"(dst), "l"(src));
}
__device__ __forceinline__ void cp_commit() { asm volatile("cp.async.commit_group;"); }
template<int N>
__device__ __forceinline__ void cp_wait() { asm volatile("cp.async.wait_group %0;" :: "n"(N)); }

// ---------------- embedding ----------------
__global__ void embed_kernel(const int* __restrict__ idx,
                             const float* __restrict__ tok,
                             const float* __restrict__ pos) {
    int bt = blockIdx.x;
    long long row = (long long)idx[bt];
    int t = bt % TT;
    const float* te = tok + row * DD;
    const float* pe = pos + (long long)t * DD;
    float* xo = g_x + (long long)bt * DD;
    for (int d = threadIdx.x; d < DD; d += blockDim.x)
        xo[d] = te[d] + pe[d];
}

// ---------------- fast transpose + cvt: fp32 [R][C] -> fp16 [C][R] --------
__global__ void transpose_cvt2(const float* __restrict__ src, __half* __restrict__ dst,
                               int R, int C) {
    __shared__ float s[64][33];
    const float* sp = src + (size_t)blockIdx.z * R * C;
    __half* dp = dst + (size_t)blockIdx.z * R * C;
    int tx = threadIdx.x, ty = threadIdx.y;
    int r0 = blockIdx.y * 64, c0 = blockIdx.x * 32;
    #pragma unroll
    for (int i = 0; i < 8; i++) {
        int rl = ty + i * 8;
        s[rl][tx] = sp[(long long)(r0 + rl) * C + c0 + tx];
    }
    __syncthreads();
    #pragma unroll
    for (int i = 0; i < 4; i++) {
        int cl = ty + i * 8;
        __half2 v = __floats2half2_rn(s[2 * tx][cl], s[2 * tx + 1][cl]);
        *reinterpret_cast<__half2*>(dp + (long long)(c0 + cl) * R + r0 + 2 * tx) = v;
    }
}

// ---------------- pack wq/wk/wv -> transposed fp16 [L][3D][D] (fused) -----
__global__ void pack_qkv_all(const float* __restrict__ wq,
                             const float* __restrict__ wk,
                             const float* __restrict__ wv) {
    __shared__ float s[64][33];
    int z = blockIdx.z;
    int m = z / (LL * HH);
    int lh = z % (LL * HH);
    int l = lh / HH, h = lh % HH;
    const float* base = (m == 0) ? wq : ((m == 1) ? wk : wv);
    const float* sp = base + (long long)lh * DD * HDD;
    __half* dp = g_wqkvT + ((long long)(l * 3 + m) * DD + h * HDD) * DD;
    int tx = threadIdx.x, ty = threadIdx.y;
    int r0 = blockIdx.y * 64, c0 = blockIdx.x * 32;   // r: d, c: hd
    #pragma unroll
    for (int i = 0; i < 8; i++) {
        int rl = ty + i * 8;
        s[rl][tx] = sp[(long long)(r0 + rl) * HDD + c0 + tx];
    }
    __syncthreads();
    #pragma unroll
    for (int i = 0; i < 4; i++) {
        int cl = ty + i * 8;
        __half2 v = __floats2half2_rn(s[2 * tx][cl], s[2 * tx + 1][cl]);
        *reinterpret_cast<__half2*>(dp + (long long)(c0 + cl) * DD + r0 + 2 * tx) = v;
    }
}

// ---------------- V transpose per layer: qkv -> vT [bh][128(pad)][T] ------
__global__ void v_transpose() {
    __shared__ __half s[32][33];
    int z = blockIdx.z;                 // b*H + h
    int b = z / HH, h = z % HH;
    int t0 = blockIdx.x * 32;
    int d0 = blockIdx.y * 32;
    int tx = threadIdx.x, ty = threadIdx.y;
    const __half* v = g_qkv + (long long)b * TT * 3 * DD + 2 * DD + h * HDD;
    #pragma unroll
    for (int i = 0; i < 4; i++) {
        int t = t0 + ty + i * 8;
        s[ty + i * 8][tx] = v[(long long)t * 3 * DD + d0 + tx];
    }
    __syncthreads();
    __half* o = g_vT + (long long)z * 128 * TT;
    #pragma unroll
    for (int i = 0; i < 4; i++) {
        int d = d0 + ty + i * 8;
        o[(long long)d * TT + t0 + tx] = s[tx][ty + i * 8];
    }
}

// ---------------- layernorm (fp32 in, fp16 out) ----------------
__global__ void ln_kernel(const float* __restrict__ in,
                          const float* __restrict__ g,
                          const float* __restrict__ b,
                          __half* __restrict__ out) {
    int row = blockIdx.x;
    const float* x = in + (long long)row * DD;
    __shared__ float rs[256];
    __shared__ float rs2[256];
    float s = 0.f, s2 = 0.f;
    for (int d = threadIdx.x; d < DD; d += 256) {
        float v = x[d];
        s += v; s2 += v * v;
    }
    rs[threadIdx.x] = s; rs2[threadIdx.x] = s2;
    __syncthreads();
    for (int o = 128; o > 0; o >>= 1) {
        if (threadIdx.x < o) { rs[threadIdx.x] += rs[threadIdx.x + o]; rs2[threadIdx.x] += rs2[threadIdx.x + o]; }
        __syncthreads();
    }
    float mean = rs[0] * (1.0f / DD);
    float var  = rs2[0] * (1.0f / DD) - mean * mean;
    float rstd = rsqrtf(var + 1e-5f);
    __half* o = out + (long long)row * DD;
    for (int d = threadIdx.x; d < DD; d += 256)
        o[d] = __float2half((x[d] - mean) * rstd * g[d] + b[d]);
}

// ---------------- flash attention (round-12 proven loop structure) --------
__global__ void __launch_bounds__(128, 2) flash_attn() {
    __shared__ __align__(16) __half Qs[FBR * 64];
    __shared__ __align__(16) __half Ks[2][FBC * 64];
    __shared__ __align__(16) __half Vs[2][64 * FBC];

    const int mt = (int)gridDim.x - 1 - (int)blockIdx.x;  // long CTAs first
    const int bmq = mt * FBR;
    const int z = blockIdx.y;                  // b*HH + h
    const int b = z / HH, h = z % HH;
    const int nsteps = mt + 1;

    const int tid  = threadIdx.x;
    const int warp = tid >> 5;
    const int lane = tid & 31;
    const int g    = lane >> 2;
    const int tig  = lane & 3;
    const int lm_i = lane >> 3;
    const int lm_r = lane & 7;
    const int wq0  = warp * 16;

    const __half* Qg = g_qkv + ((long long)b * TT + bmq) * 3 * DD + h * HDD;
    const __half* Kg = g_qkv + (long long)b * TT * 3 * DD + DD + h * HDD;
    const __half* Vg = g_vT + (long long)z * 128 * TT;

    const unsigned sQ = (unsigned)__cvta_generic_to_shared(Qs);
    const unsigned sK = (unsigned)__cvta_generic_to_shared(&Ks[0][0]);
    const unsigned sV = (unsigned)__cvta_generic_to_shared(&Vs[0][0]);

    #pragma unroll
    for (int p = 0; p < 4; p++) {
        int i = p * 128 + tid;
        int row = i >> 3, ch = i & 7;
        cp16(sQ + fsw(row, ch), Qg + (long long)row * 3 * DD + ch * 8);
    }
    cp_commit();

    auto loadKV = [&](int buf, int s0) {
        #pragma unroll
        for (int p = 0; p < 4; p++) {
            int i = p * 128 + tid;
            int row = i >> 3, ch = i & 7;
            cp16(sK + buf * 8192 + fsw(row, ch), Kg + (long long)(s0 + row) * 3 * DD + ch * 8);
        }
        #pragma unroll
        for (int p = 0; p < 4; p++) {
            int i = p * 128 + tid;
            int row = i >> 3, ch = i & 7;
            cp16(sV + buf * 8192 + fsw(row, ch), Vg + (long long)row * TT + s0 + ch * 8);
        }
        cp_commit();
    };

    loadKV(0, 0);

    unsigned qf[4][4];
    float oacc[8][4];
    #pragma unroll
    for (int j = 0; j < 8; j++)
        #pragma unroll
        for (int q = 0; q < 4; q++) oacc[j][q] = 0.f;
    float m2[2] = {-1e30f, -1e30f};
    float l2[2] = {0.f, 0.f};
    const int t0 = bmq + wq0 + g;
    const int t1 = t0 + 8;

    for (int it = 0; it < nsteps; it++) {
        int buf = it & 1;
        if (it + 1 < nsteps) { loadKV(buf ^ 1, (it + 1) * FBC); cp_wait<1>(); }
        else                 { cp_wait<0>(); }
        __syncthreads();

        if (it == 0) {
            #pragma unroll
            for (int ks = 0; ks < 4; ks++) {
                int row = wq0 + (lm_i & 1) * 8 + lm_r;
                int ch  = ks * 2 + (lm_i >> 1);
                ldsm4(qf[ks][0], qf[ks][1], qf[ks][2], qf[ks][3], sQ + fsw(row, ch));
            }
        }

        float sacc[8][4];
        #pragma unroll
        for (int j = 0; j < 8; j++)
            #pragma unroll
            for (int q = 0; q < 4; q++) sacc[j][q] = 0.f;
        #pragma unroll
        for (int ks = 0; ks < 4; ks++) {
            #pragma unroll
            for (int njp = 0; njp < 4; njp++) {
                unsigned bb[4];
                int row = njp * 16 + (lm_i >> 1) * 8 + lm_r;
                int ch  = ks * 2 + (lm_i & 1);
                ldsm4(bb[0], bb[1], bb[2], bb[3], sK + buf * 8192 + fsw(row, ch));
                mma_f16(sacc[2 * njp],     qf[ks], bb);
                mma_f16(sacc[2 * njp + 1], qf[ks], bb + 2);
            }
        }

        const bool last = (it == nsteps - 1);
        const int s0 = it * FBC;
        float mx0 = m2[0], mx1 = m2[1];
        #pragma unroll
        for (int nj = 0; nj < 8; nj++) {
            float v0 = sacc[nj][0] * 0.125f;
            float v1 = sacc[nj][1] * 0.125f;
            float v2 = sacc[nj][2] * 0.125f;
            float v3 = sacc[nj][3] * 0.125f;
            if (last) {
                int c0 = s0 + nj * 8 + 2 * tig, c1 = c0 + 1;
                if (c0 > t0) v0 = -1e30f;
                if (c1 > t0) v1 = -1e30f;
                if (c0 > t1) v2 = -1e30f;
                if (c1 > t1) v3 = -1e30f;
            }
            sacc[nj][0] = v0; sacc[nj][1] = v1; sacc[nj][2] = v2; sacc[nj][3] = v3;
            mx0 = fmaxf(mx0, fmaxf(v0, v1));
            mx1 = fmaxf(mx1, fmaxf(v2, v3));
        }
        mx0 = fmaxf(mx0, __shfl_xor_sync(0xffffffff, mx0, 1));
        mx0 = fmaxf(mx0, __shfl_xor_sync(0xffffffff, mx0, 2));
        mx1 = fmaxf(mx1, __shfl_xor_sync(0xffffffff, mx1, 1));
        mx1 = fmaxf(mx1, __shfl_xor_sync(0xffffffff, mx1, 2));
        float sc0 = __expf(m2[0] - mx0);
        float sc1 = __expf(m2[1] - mx1);
        m2[0] = mx0; m2[1] = mx1;
        float sum0 = 0.f, sum1 = 0.f;
        unsigned pf[8][2];
        #pragma unroll
        for (int nj = 0; nj < 8; nj++) {
            float p0 = __expf(sacc[nj][0] - mx0);
            float p1 = __expf(sacc[nj][1] - mx0);
            float p2 = __expf(sacc[nj][2] - mx1);
            float p3 = __expf(sacc[nj][3] - mx1);
            sum0 += p0 + p1; sum1 += p2 + p3;
            __half2 h0 = __floats2half2_rn(p0, p1);
            __half2 h1 = __floats2half2_rn(p2, p3);
            pf[nj][0] = *reinterpret_cast<unsigned*>(&h0);
            pf[nj][1] = *reinterpret_cast<unsigned*>(&h1);
        }
        sum0 += __shfl_xor_sync(0xffffffff, sum0, 1);
        sum0 += __shfl_xor_sync(0xffffffff, sum0, 2);
        sum1 += __shfl_xor_sync(0xffffffff, sum1, 1);
        sum1 += __shfl_xor_sync(0xffffffff, sum1, 2);
        l2[0] = l2[0] * sc0 + sum0;
        l2[1] = l2[1] * sc1 + sum1;
        #pragma unroll
        for (int nj = 0; nj < 8; nj++) {
            oacc[nj][0] *= sc0; oacc[nj][1] *= sc0;
            oacc[nj][2] *= sc1; oacc[nj][3] *= sc1;
        }

        #pragma unroll
        for (int j = 0; j < 4; j++) {
            unsigned af[4] = {pf[2 * j][0], pf[2 * j][1], pf[2 * j + 1][0], pf[2 * j + 1][1]};
            #pragma unroll
            for (int njp = 0; njp < 4; njp++) {
                unsigned bb[4];
                int row = njp * 16 + (lm_i >> 1) * 8 + lm_r;
                int ch  = j * 2 + (lm_i & 1);
                ldsm4(bb[0], bb[1], bb[2], bb[3], sV + buf * 8192 + fsw(row, ch));
                mma_f16(oacc[2 * njp],     af, bb);
                mma_f16(oacc[2 * njp + 1], af, bb + 2);
            }
        }
        __syncthreads();
    }

    float inv0 = 1.0f / l2[0];
    float inv1 = 1.0f / l2[1];
    __half* O0 = g_attn + ((long long)b * TT + t0) * DD + h * HDD;
    __half* O1 = g_attn + ((long long)b * TT + t1) * DD + h * HDD;
    #pragma unroll
    for (int nj = 0; nj < 8; nj++) {
        int col = nj * 8 + 2 * tig;
        __half2 h0 = __floats2half2_rn(oacc[nj][0] * inv0, oacc[nj][1] * inv0);
        __half2 h1 = __floats2half2_rn(oacc[nj][2] * inv1, oacc[nj][3] * inv1);
        *reinterpret_cast<__half2*>(O0 + col) = h0;
        *reinterpret_cast<__half2*>(O1 + col) = h1;
    }
}

// ---------------- fp16 tensor-core GEMM, templated BN (128 or 64) ---------
// BNN=128: 2x2 warps of 64x64. BNN=64: 2x2 warps of 64x32 (wave-fill variant).
template<int EPI, bool OUTH, int BNN>
__global__ void __launch_bounds__(128, 2)
mma_gemm(const __half* __restrict__ A, const __half* __restrict__ B,
         const float* __restrict__ bias, const float* __restrict__ aux,
         void* __restrict__ Cv,
         int M, int N, int K, int lda, int ldb, int ldc) {
    constexpr int WN  = BNN / 2;    // warp n extent
    constexpr int NJP = BNN / 32;   // ldsm.x4 groups per warp (16 rows each)
    constexpr int NJ  = BNN / 16;   // 8-col accum tiles per warp

    __shared__ __align__(16) unsigned As[NS][BM * 16];
    __shared__ __align__(16) unsigned Bs[NS][BNN * 16];

    const int bm = blockIdx.x * BM;
    const int bn = blockIdx.y * BNN;
    const int nIter = K / BK;

    const int tid  = threadIdx.x;
    const int warp = tid >> 5;
    const int lane = tid & 31;
    const int g    = lane >> 2;
    const int tig  = lane & 3;
    const int wm   = (warp & 1) * 64;
    const int wn   = (warp >> 1) * WN;

    const unsigned sA = (unsigned)__cvta_generic_to_shared(&As[0][0]);
    const unsigned sB = (unsigned)__cvta_generic_to_shared(&Bs[0][0]);

    const int lm_i = lane >> 3;
    const int lm_r = lane & 7;
    const int l_r = tid >> 2;
    const int l_c = tid & 3;

    auto issueLoads = [&](int stage, int k0) {
        #pragma unroll
        for (int p = 0; p < 4; p++) {
            int r = p * 32 + l_r;
            unsigned dst = sA + (unsigned)((stage * BM * 16 + sw_idx(r, l_c, 0)) * 4);
            cp16(dst, A + (long long)(bm + r) * lda + (k0 + l_c * 8));
        }
        #pragma unroll
        for (int p = 0; p < BNN / 32; p++) {
            int r = p * 32 + l_r;
            unsigned dst = sB + (unsigned)((stage * BNN * 16 + sw_idx(r, l_c, 0)) * 4);
            cp16(dst, B + (long long)(bn + r) * ldb + (k0 + l_c * 8));
        }
    };

    float acc[4][NJ][4];
    #pragma unroll
    for (int i = 0; i < 4; i++)
        #pragma unroll
        for (int j = 0; j < NJ; j++)
            #pragma unroll
            for (int q = 0; q < 4; q++) acc[i][j][q] = 0.f;

    issueLoads(0, 0);
    cp_commit();
    if (nIter > 1) { issueLoads(1, BK); cp_commit(); }

    for (int it = 0; it < nIter; it++) {
        int buf = it % NS;
        if (it + 2 < nIter) {
            issueLoads((it + 2) % NS, (it + 2) * BK);
            cp_commit();
            cp_wait<2>();
        } else if (it + 1 < nIter) {
            cp_wait<1>();
        } else {
            cp_wait<0>();
        }
        __syncthreads();

        #pragma unroll
        for (int ks = 0; ks < 2; ks++) {
            unsigned af[4][4];
            #pragma unroll
            for (int mi = 0; mi < 4; mi++) {
                int row = wm + mi * 16 + (lm_i & 1) * 8 + lm_r;
                int chunk = ks * 2 + (lm_i >> 1);
                unsigned addr = sA + (unsigned)((buf * BM * 16 + sw_idx(row, chunk, 0)) * 4);
                ldsm4(af[mi][0], af[mi][1], af[mi][2], af[mi][3], addr);
            }
            #pragma unroll
            for (int njp = 0; njp < NJP; njp++) {
                unsigned bb[4];
                int row = wn + njp * 16 + (lm_i >> 1) * 8 + lm_r;
                int chunk = ks * 2 + (lm_i & 1);
                unsigned addr = sB + (unsigned)((buf * BNN * 16 + sw_idx(row, chunk, 0)) * 4);
                ldsm4(bb[0], bb[1], bb[2], bb[3], addr);
                #pragma unroll
                for (int mi = 0; mi < 4; mi++) {
                    mma_f16(acc[mi][2 * njp],     af[mi], bb);
                    mma_f16(acc[mi][2 * njp + 1], af[mi], bb + 2);
                }
            }
        }
        __syncthreads();
    }

    #pragma unroll
    for (int mi = 0; mi < 4; mi++) {
        int row = bm + wm + mi * 16 + g;
        #pragma unroll
        for (int nj = 0; nj < NJ; nj++) {
            int col = bn + wn + nj * 8 + tig * 2;
            if (col >= N) continue;
            float v0 = acc[mi][nj][0];
            float v1 = acc[mi][nj][1];
            float v2 = acc[mi][nj][2];
            float v3 = acc[mi][nj][3];
            if (EPI >= 1) {
                float bb0 = bias[col];
                float bb1 = bias[col + 1];
                v0 += bb0; v1 += bb1; v2 += bb0; v3 += bb1;
            }
            if (EPI == 2) {
                v0 = fmaxf(v0, 0.f); v1 = fmaxf(v1, 0.f);
                v2 = fmaxf(v2, 0.f); v3 = fmaxf(v3, 0.f);
            }
            if (EPI == 3) {
                float2 a0 = *reinterpret_cast<const float2*>(aux + (long long)row * ldc + col);
                float2 a1 = *reinterpret_cast<const float2*>(aux + (long long)(row + 8) * ldc + col);
                v0 += a0.x; v1 += a0.y; v2 += a1.x; v3 += a1.y;
            }
            if (OUTH) {
                __half* C = (__half*)Cv;
                *reinterpret_cast<__half2*>(C + (long long)row * ldc + col) =
                    __floats2half2_rn(v0, v1);
                *reinterpret_cast<__half2*>(C + (long long)(row + 8) * ldc + col) =
                    __floats2half2_rn(v2, v3);
            } else {
                float* C = (float*)Cv;
                *reinterpret_cast<float2*>(C + (long long)row * ldc + col)       = make_float2(v0, v1);
                *reinterpret_cast<float2*>(C + (long long)(row + 8) * ldc + col) = make_float2(v2, v3);
            }
        }
    }
}

extern "C" void kernel_launch(void* const* d_in, const int* in_sizes, int n_in,
                              void* d_out, int out_size) {
    const int*   idx     = (const int*)d_in[0];
    const float* tok_emb = (const float*)d_in[1];
    const float* pos_emb = (const float*)d_in[2];
    const float* wq      = (const float*)d_in[3];
    const float* wk      = (const float*)d_in[4];
    const float* wv      = (const float*)d_in[5];
    const float* w_proj  = (const float*)d_in[6];
    const float* b_proj  = (const float*)d_in[7];
    const float* w1      = (const float*)d_in[8];
    const float* b1      = (const float*)d_in[9];
    const float* w2      = (const float*)d_in[10];
    const float* b2      = (const float*)d_in[11];
    const float* ln1_g   = (const float*)d_in[12];
    const float* ln1_b   = (const float*)d_in[13];
    const float* ln2_g   = (const float*)d_in[14];
    const float* ln2_b   = (const float*)d_in[15];
    const float* lnf_g   = (const float*)d_in[16];
    const float* lnf_b   = (const float*)d_in[17];
    const float* w_lm    = (const float*)d_in[18];
    const float* b_lm    = (const float*)d_in[19];
    float* out = (float*)d_out;

    float  *px, *psa;
    __half *ph, *pqkv, *pattn, *pff1;
    __half *pwqkvT, *pwprojT, *pw1T, *pw2T, *pwlmT;
    cudaGetSymbolAddress((void**)&px,      g_x);
    cudaGetSymbolAddress((void**)&ph,      g_h);
    cudaGetSymbolAddress((void**)&pqkv,    g_qkv);
    cudaGetSymbolAddress((void**)&pattn,   g_attn);
    cudaGetSymbolAddress((void**)&psa,     g_sa);
    cudaGetSymbolAddress((void**)&pff1,    g_ff1);
    cudaGetSymbolAddress((void**)&pwqkvT,  g_wqkvT);
    cudaGetSymbolAddress((void**)&pwprojT, g_wprojT);
    cudaGetSymbolAddress((void**)&pw1T,    g_w1T);
    cudaGetSymbolAddress((void**)&pw2T,    g_w2T);
    cudaGetSymbolAddress((void**)&pwlmT,   g_wlmT);

    // ---- weight prep: transpose + fp16 cvt (half2 writes, fused qkv) ----
    {
        dim3 th(32, 8);
        pack_qkv_all<<<dim3(HDD/32, DD/64, 3*LL*HH), th>>>(wq, wk, wv);
        transpose_cvt2<<<dim3(DD/32,  DD/64,  LL), th>>>(w_proj, pwprojT, DD,  DD);
        transpose_cvt2<<<dim3(FFD/32, DD/64,  LL), th>>>(w1,     pw1T,    DD,  FFD);
        transpose_cvt2<<<dim3(DD/32,  FFD/64, LL), th>>>(w2,     pw2T,    FFD, DD);
        transpose_cvt2<<<dim3(VV/32,  DD/64,  1),  th>>>(w_lm,   pwlmT,   DD,  VV);
    }
    embed_kernel<<<BT, 256>>>(idx, tok_emb, pos_emb);

    for (int l = 0; l < LL; l++) {
        ln_kernel<<<BT, 256>>>(px, ln1_g + (long long)l*DD, ln1_b + (long long)l*DD, ph);

        // qkv = h @ wqkvT^T  -> fp16
        mma_gemm<0,true,128><<<dim3(BT/BM, 3*DD/128), 128>>>(
            ph, pwqkvT + (long long)l*3*DD*DD, nullptr, nullptr, pqkv,
            BT, 3*DD, DD, DD, DD, 3*DD);

        // vT per head
        v_transpose<<<dim3(TT/32, HDD/32, BB*HH), dim3(32, 8)>>>();

        // fused attention -> g_attn
        flash_attn<<<dim3(TT/FBR, BB*HH), 128>>>();

        // sa = attn @ w_proj + b_proj -> fp32  (BN=64: 256 CTAs, single wave)
        mma_gemm<1,false,64><<<dim3(BT/BM, DD/64), 128>>>(
            pattn, pwprojT + (long long)l*DD*DD, b_proj + (long long)l*DD, nullptr, psa,
            BT, DD, DD, DD, DD, DD);

        ln_kernel<<<BT, 256>>>(px, ln2_g + (long long)l*DD, ln2_b + (long long)l*DD, ph);

        // ff1 = relu(h @ w1 + b1) -> fp16
        mma_gemm<2,true,128><<<dim3(BT/BM, FFD/128), 128>>>(
            ph, pw1T + (long long)l*FFD*DD, b1 + (long long)l*FFD, nullptr, pff1,
            BT, FFD, DD, DD, DD, FFD);

        // x = ff1 @ w2 + b2 + sa  (residual fused) -> fp32  (BN=64 variant)
        mma_gemm<3,false,64><<<dim3(BT/BM, DD/64), 128>>>(
            pff1, pw2T + (long long)l*DD*FFD, b2 + (long long)l*DD, psa, px,
            BT, DD, FFD, FFD, FFD, DD);
    }

    ln_kernel<<<BT, 256>>>(px, lnf_g, lnf_b, ph);

    // logits = h @ w_lm + b_lm -> fp32
    mma_gemm<1,false,128><<<dim3(BT/BM, VV/128), 128>>>(
        ph, pwlmT, b_lm, nullptr, out,
        BT, VV, DD, DD, DD, VV);
}

// round 16
// speedup vs baseline: 1.1773x; 1.0165x over previous
#include <cuda_runtime.h>
#include <cuda_fp16.h>
#include <math.h>

// Problem constants
#define BB  2
#define TT  1024
#define DD  1024
#define HH  16
#define HDD 64
#define LL  3
#define VV  32000
#define FFD 4096
#define BT  (BB*TT)

#define BM 128
#define BK 64           // dense GEMM k-slab (4 x k16 per stage)
#define NS 3            // cp.async pipeline stages (dense GEMM)
#define FBR 64          // flash-attn Q rows per CTA
#define FBC 64          // flash-attn KV cols per step

// ---------------- static scratch (allocation-free) ----------------
__device__ float  g_x   [BT*DD];                       // fp32 residual stream
__device__ __half g_h   [BT*DD];                       // LN output
__device__ __half g_qkv [BT*3*DD];
__device__ __half g_attn[BT*DD];
__device__ float  g_sa  [BT*DD];
__device__ __half g_ff1 [(size_t)BT*FFD];
__device__ __half g_vT  [(size_t)BB*HH*128*TT];        // V transposed, padded
// fp16 transposed weights
__device__ __half g_wqkvT [(size_t)LL*3*DD*DD];        // [l][n=3D][k=D]
__device__ __half g_wprojT[(size_t)LL*DD*DD];
__device__ __half g_w1T   [(size_t)LL*FFD*DD];
__device__ __half g_w2T   [(size_t)LL*DD*FFD];
__device__ __half g_wlmT  [(size_t)VV*DD];

// ---------------- helpers ----------------
__device__ __forceinline__ void mma_f16(float* c, const unsigned* a, const unsigned* b) {
    asm volatile(
        "mma.sync.aligned.m16n8k16.row.col.f32.f16.f16.f32 "
        "{%0,%1,%2,%3},{%4,%5,%6,%7},{%8,%9},{%0,%1,%2,%3};"
        : "+f"(c[0]), "+f"(c[1]), "+f"(c[2]), "+f"(c[3])
        : "r"(a[0]), "r"(a[1]), "r"(a[2]), "r"(a[3]), "r"(b[0]), "r"(b[1]));
}

__device__ __forceinline__ void ldsm4(unsigned& r0, unsigned& r1, unsigned& r2, unsigned& r3,
                                      unsigned addr) {
    asm volatile("ldmatrix.sync.aligned.m8n8.x4.shared.b16 {%0,%1,%2,%3}, [%4];"
                 : "=r"(r0), "=r"(r1), "=r"(r2), "=r"(r3) : "r"(addr));
}

// tile with 64-half (128B) rows, 8 chunks of 16B. byte offset.
// phys chunk = chunk ^ (row & 7) -> conflict-free cp.async stores + LDSM.
__device__ __forceinline__ int fsw(int row, int chunk) {
    return row * 128 + ((chunk ^ (row & 7)) << 4);
}

__device__ __forceinline__ void cp16(unsigned dst, const void* src) {
    asm volatile("cp.async.cg.shared.global [%0], [%1], 16;" :: "r"(dst), "l"(src));
}
__device__ __forceinline__ void cp_commit() { asm volatile("cp.async.commit_group;"); }
template<int N>
__device__ __forceinline__ void cp_wait() { asm volatile("cp.async.wait_group %0;" :: "n"(N)); }

// ---------------- embedding ----------------
__global__ void embed_kernel(const int* __restrict__ idx,
                             const float* __restrict__ tok,
                             const float* __restrict__ pos) {
    int bt = blockIdx.x;
    long long row = (long long)idx[bt];
    int t = bt % TT;
    const float* te = tok + row * DD;
    const float* pe = pos + (long long)t * DD;
    float* xo = g_x + (long long)bt * DD;
    for (int d = threadIdx.x; d < DD; d += blockDim.x)
        xo[d] = te[d] + pe[d];
}

// ---------------- fast transpose + cvt: fp32 [R][C] -> fp16 [C][R] --------
__global__ void transpose_cvt2(const float* __restrict__ src, __half* __restrict__ dst,
                               int R, int C) {
    __shared__ float s[64][33];
    const float* sp = src + (size_t)blockIdx.z * R * C;
    __half* dp = dst + (size_t)blockIdx.z * R * C;
    int tx = threadIdx.x, ty = threadIdx.y;
    int r0 = blockIdx.y * 64, c0 = blockIdx.x * 32;
    #pragma unroll
    for (int i = 0; i < 8; i++) {
        int rl = ty + i * 8;
        s[rl][tx] = sp[(long long)(r0 + rl) * C + c0 + tx];
    }
    __syncthreads();
    #pragma unroll
    for (int i = 0; i < 4; i++) {
        int cl = ty + i * 8;
        __half2 v = __floats2half2_rn(s[2 * tx][cl], s[2 * tx + 1][cl]);
        *reinterpret_cast<__half2*>(dp + (long long)(c0 + cl) * R + r0 + 2 * tx) = v;
    }
}

// ---------------- pack wq/wk/wv -> transposed fp16 [L][3D][D] (fused) -----
__global__ void pack_qkv_all(const float* __restrict__ wq,
                             const float* __restrict__ wk,
                             const float* __restrict__ wv) {
    __shared__ float s[64][33];
    int z = blockIdx.z;
    int m = z / (LL * HH);
    int lh = z % (LL * HH);
    int l = lh / HH, h = lh % HH;
    const float* base = (m == 0) ? wq : ((m == 1) ? wk : wv);
    const float* sp = base + (long long)lh * DD * HDD;
    __half* dp = g_wqkvT + ((long long)(l * 3 + m) * DD + h * HDD) * DD;
    int tx = threadIdx.x, ty = threadIdx.y;
    int r0 = blockIdx.y * 64, c0 = blockIdx.x * 32;   // r: d, c: hd
    #pragma unroll
    for (int i = 0; i < 8; i++) {
        int rl = ty + i * 8;
        s[rl][tx] = sp[(long long)(r0 + rl) * HDD + c0 + tx];
    }
    __syncthreads();
    #pragma unroll
    for (int i = 0; i < 4; i++) {
        int cl = ty + i * 8;
        __half2 v = __floats2half2_rn(s[2 * tx][cl], s[2 * tx + 1][cl]);
        *reinterpret_cast<__half2*>(dp + (long long)(c0 + cl) * DD + r0 + 2 * tx) = v;
    }
}

// ---------------- V transpose per layer: qkv -> vT [bh][128(pad)][T] ------
__global__ void v_transpose() {
    __shared__ __half s[32][33];
    int z = blockIdx.z;                 // b*H + h
    int b = z / HH, h = z % HH;
    int t0 = blockIdx.x * 32;
    int d0 = blockIdx.y * 32;
    int tx = threadIdx.x, ty = threadIdx.y;
    const __half* v = g_qkv + (long long)b * TT * 3 * DD + 2 * DD + h * HDD;
    #pragma unroll
    for (int i = 0; i < 4; i++) {
        int t = t0 + ty + i * 8;
        s[ty + i * 8][tx] = v[(long long)t * 3 * DD + d0 + tx];
    }
    __syncthreads();
    __half* o = g_vT + (long long)z * 128 * TT;
    #pragma unroll
    for (int i = 0; i < 4; i++) {
        int d = d0 + ty + i * 8;
        o[(long long)d * TT + t0 + tx] = s[tx][ty + i * 8];
    }
}

// ---------------- layernorm (fp32 in, fp16 out) ----------------
__global__ void ln_kernel(const float* __restrict__ in,
                          const float* __restrict__ g,
                          const float* __restrict__ b,
                          __half* __restrict__ out) {
    int row = blockIdx.x;
    const float* x = in + (long long)row * DD;
    __shared__ float rs[256];
    __shared__ float rs2[256];
    float s = 0.f, s2 = 0.f;
    for (int d = threadIdx.x; d < DD; d += 256) {
        float v = x[d];
        s += v; s2 += v * v;
    }
    rs[threadIdx.x] = s; rs2[threadIdx.x] = s2;
    __syncthreads();
    for (int o = 128; o > 0; o >>= 1) {
        if (threadIdx.x < o) { rs[threadIdx.x] += rs[threadIdx.x + o]; rs2[threadIdx.x] += rs2[threadIdx.x + o]; }
        __syncthreads();
    }
    float mean = rs[0] * (1.0f / DD);
    float var  = rs2[0] * (1.0f / DD) - mean * mean;
    float rstd = rsqrtf(var + 1e-5f);
    __half* o = out + (long long)row * DD;
    for (int d = threadIdx.x; d < DD; d += 256)
        o[d] = __float2half((x[d] - mean) * rstd * g[d] + b[d]);
}

// ---------------- flash attention (round-12 proven loop structure) --------
__global__ void __launch_bounds__(128, 2) flash_attn() {
    __shared__ __align__(16) __half Qs[FBR * 64];
    __shared__ __align__(16) __half Ks[2][FBC * 64];
    __shared__ __align__(16) __half Vs[2][64 * FBC];

    const int mt = (int)gridDim.x - 1 - (int)blockIdx.x;  // long CTAs first
    const int bmq = mt * FBR;
    const int z = blockIdx.y;                  // b*HH + h
    const int b = z / HH, h = z % HH;
    const int nsteps = mt + 1;

    const int tid  = threadIdx.x;
    const int warp = tid >> 5;
    const int lane = tid & 31;
    const int g    = lane >> 2;
    const int tig  = lane & 3;
    const int lm_i = lane >> 3;
    const int lm_r = lane & 7;
    const int wq0  = warp * 16;

    const __half* Qg = g_qkv + ((long long)b * TT + bmq) * 3 * DD + h * HDD;
    const __half* Kg = g_qkv + (long long)b * TT * 3 * DD + DD + h * HDD;
    const __half* Vg = g_vT + (long long)z * 128 * TT;

    const unsigned sQ = (unsigned)__cvta_generic_to_shared(Qs);
    const unsigned sK = (unsigned)__cvta_generic_to_shared(&Ks[0][0]);
    const unsigned sV = (unsigned)__cvta_generic_to_shared(&Vs[0][0]);

    #pragma unroll
    for (int p = 0; p < 4; p++) {
        int i = p * 128 + tid;
        int row = i >> 3, ch = i & 7;
        cp16(sQ + fsw(row, ch), Qg + (long long)row * 3 * DD + ch * 8);
    }
    cp_commit();

    auto loadKV = [&](int buf, int s0) {
        #pragma unroll
        for (int p = 0; p < 4; p++) {
            int i = p * 128 + tid;
            int row = i >> 3, ch = i & 7;
            cp16(sK + buf * 8192 + fsw(row, ch), Kg + (long long)(s0 + row) * 3 * DD + ch * 8);
        }
        #pragma unroll
        for (int p = 0; p < 4; p++) {
            int i = p * 128 + tid;
            int row = i >> 3, ch = i & 7;
            cp16(sV + buf * 8192 + fsw(row, ch), Vg + (long long)row * TT + s0 + ch * 8);
        }
        cp_commit();
    };

    loadKV(0, 0);

    unsigned qf[4][4];
    float oacc[8][4];
    #pragma unroll
    for (int j = 0; j < 8; j++)
        #pragma unroll
        for (int q = 0; q < 4; q++) oacc[j][q] = 0.f;
    float m2[2] = {-1e30f, -1e30f};
    float l2[2] = {0.f, 0.f};
    const int t0 = bmq + wq0 + g;
    const int t1 = t0 + 8;

    for (int it = 0; it < nsteps; it++) {
        int buf = it & 1;
        if (it + 1 < nsteps) { loadKV(buf ^ 1, (it + 1) * FBC); cp_wait<1>(); }
        else                 { cp_wait<0>(); }
        __syncthreads();

        if (it == 0) {
            #pragma unroll
            for (int ks = 0; ks < 4; ks++) {
                int row = wq0 + (lm_i & 1) * 8 + lm_r;
                int ch  = ks * 2 + (lm_i >> 1);
                ldsm4(qf[ks][0], qf[ks][1], qf[ks][2], qf[ks][3], sQ + fsw(row, ch));
            }
        }

        float sacc[8][4];
        #pragma unroll
        for (int j = 0; j < 8; j++)
            #pragma unroll
            for (int q = 0; q < 4; q++) sacc[j][q] = 0.f;
        #pragma unroll
        for (int ks = 0; ks < 4; ks++) {
            #pragma unroll
            for (int njp = 0; njp < 4; njp++) {
                unsigned bb[4];
                int row = njp * 16 + (lm_i >> 1) * 8 + lm_r;
                int ch  = ks * 2 + (lm_i & 1);
                ldsm4(bb[0], bb[1], bb[2], bb[3], sK + buf * 8192 + fsw(row, ch));
                mma_f16(sacc[2 * njp],     qf[ks], bb);
                mma_f16(sacc[2 * njp + 1], qf[ks], bb + 2);
            }
        }

        const bool last = (it == nsteps - 1);
        const int s0 = it * FBC;
        float mx0 = m2[0], mx1 = m2[1];
        #pragma unroll
        for (int nj = 0; nj < 8; nj++) {
            float v0 = sacc[nj][0] * 0.125f;
            float v1 = sacc[nj][1] * 0.125f;
            float v2 = sacc[nj][2] * 0.125f;
            float v3 = sacc[nj][3] * 0.125f;
            if (last) {
                int c0 = s0 + nj * 8 + 2 * tig, c1 = c0 + 1;
                if (c0 > t0) v0 = -1e30f;
                if (c1 > t0) v1 = -1e30f;
                if (c0 > t1) v2 = -1e30f;
                if (c1 > t1) v3 = -1e30f;
            }
            sacc[nj][0] = v0; sacc[nj][1] = v1; sacc[nj][2] = v2; sacc[nj][3] = v3;
            mx0 = fmaxf(mx0, fmaxf(v0, v1));
            mx1 = fmaxf(mx1, fmaxf(v2, v3));
        }
        mx0 = fmaxf(mx0, __shfl_xor_sync(0xffffffff, mx0, 1));
        mx0 = fmaxf(mx0, __shfl_xor_sync(0xffffffff, mx0, 2));
        mx1 = fmaxf(mx1, __shfl_xor_sync(0xffffffff, mx1, 1));
        mx1 = fmaxf(mx1, __shfl_xor_sync(0xffffffff, mx1, 2));
        float sc0 = __expf(m2[0] - mx0);
        float sc1 = __expf(m2[1] - mx1);
        m2[0] = mx0; m2[1] = mx1;
        float sum0 = 0.f, sum1 = 0.f;
        unsigned pf[8][2];
        #pragma unroll
        for (int nj = 0; nj < 8; nj++) {
            float p0 = __expf(sacc[nj][0] - mx0);
            float p1 = __expf(sacc[nj][1] - mx0);
            float p2 = __expf(sacc[nj][2] - mx1);
            float p3 = __expf(sacc[nj][3] - mx1);
            sum0 += p0 + p1; sum1 += p2 + p3;
            __half2 h0 = __floats2half2_rn(p0, p1);
            __half2 h1 = __floats2half2_rn(p2, p3);
            pf[nj][0] = *reinterpret_cast<unsigned*>(&h0);
            pf[nj][1] = *reinterpret_cast<unsigned*>(&h1);
        }
        sum0 += __shfl_xor_sync(0xffffffff, sum0, 1);
        sum0 += __shfl_xor_sync(0xffffffff, sum0, 2);
        sum1 += __shfl_xor_sync(0xffffffff, sum1, 1);
        sum1 += __shfl_xor_sync(0xffffffff, sum1, 2);
        l2[0] = l2[0] * sc0 + sum0;
        l2[1] = l2[1] * sc1 + sum1;
        #pragma unroll
        for (int nj = 0; nj < 8; nj++) {
            oacc[nj][0] *= sc0; oacc[nj][1] *= sc0;
            oacc[nj][2] *= sc1; oacc[nj][3] *= sc1;
        }

        #pragma unroll
        for (int j = 0; j < 4; j++) {
            unsigned af[4] = {pf[2 * j][0], pf[2 * j][1], pf[2 * j + 1][0], pf[2 * j + 1][1]};
            #pragma unroll
            for (int njp = 0; njp < 4; njp++) {
                unsigned bb[4];
                int row = njp * 16 + (lm_i >> 1) * 8 + lm_r;
                int ch  = j * 2 + (lm_i & 1);
                ldsm4(bb[0], bb[1], bb[2], bb[3], sV + buf * 8192 + fsw(row, ch));
                mma_f16(oacc[2 * njp],     af, bb);
                mma_f16(oacc[2 * njp + 1], af, bb + 2);
            }
        }
        __syncthreads();
    }

    float inv0 = 1.0f / l2[0];
    float inv1 = 1.0f / l2[1];
    __half* O0 = g_attn + ((long long)b * TT + t0) * DD + h * HDD;
    __half* O1 = g_attn + ((long long)b * TT + t1) * DD + h * HDD;
    #pragma unroll
    for (int nj = 0; nj < 8; nj++) {
        int col = nj * 8 + 2 * tig;
        __half2 h0 = __floats2half2_rn(oacc[nj][0] * inv0, oacc[nj][1] * inv0);
        __half2 h1 = __floats2half2_rn(oacc[nj][2] * inv1, oacc[nj][3] * inv1);
        *reinterpret_cast<__half2*>(O0 + col) = h0;
        *reinterpret_cast<__half2*>(O1 + col) = h1;
    }
}

// ---------------- fp16 tensor-core GEMM, BK=64, dynamic smem --------------
// BNN=128: 2x2 warps of 64x64. BNN=64: 2x2 warps of 64x32.
// Stage: A 128x64h (16KB, fsw rows) + B BNNx64h. NS=3 stages.
template<int EPI, bool OUTH, int BNN>
__global__ void __launch_bounds__(128, 2)
mma_gemm(const __half* __restrict__ A, const __half* __restrict__ B,
         const float* __restrict__ bias, const float* __restrict__ aux,
         void* __restrict__ Cv,
         int M, int N, int K, int lda, int ldb, int ldc) {
    constexpr int WN  = BNN / 2;
    constexpr int NJP = BNN / 32;
    constexpr int NJ  = BNN / 16;
    constexpr int ABYTES = BM * 128;        // 16384
    constexpr int BBYTES = BNN * 128;

    extern __shared__ __align__(16) char dsm[];
    const unsigned sA = (unsigned)__cvta_generic_to_shared(dsm);
    const unsigned sB = sA + NS * ABYTES;

    const int bm = blockIdx.x * BM;
    const int bn = blockIdx.y * BNN;
    const int nIter = K / BK;

    const int tid  = threadIdx.x;
    const int warp = tid >> 5;
    const int lane = tid & 31;
    const int g    = lane >> 2;
    const int tig  = lane & 3;
    const int wm   = (warp & 1) * 64;
    const int wn   = (warp >> 1) * WN;

    const int lm_i = lane >> 3;
    const int lm_r = lane & 7;
    const int l_r = tid >> 3;        // 0..15 (+p*16)
    const int l_c = tid & 7;         // chunk 0..7

    auto issueLoads = [&](int stage, int k0) {
        #pragma unroll
        for (int p = 0; p < 8; p++) {
            int r = p * 16 + l_r;
            cp16(sA + stage * ABYTES + fsw(r, l_c),
                 A + (long long)(bm + r) * lda + (k0 + l_c * 8));
        }
        #pragma unroll
        for (int p = 0; p < BNN / 16; p++) {
            int r = p * 16 + l_r;
            cp16(sB + stage * BBYTES + fsw(r, l_c),
                 B + (long long)(bn + r) * ldb + (k0 + l_c * 8));
        }
        cp_commit();
    };

    float acc[4][NJ][4];
    #pragma unroll
    for (int i = 0; i < 4; i++)
        #pragma unroll
        for (int j = 0; j < NJ; j++)
            #pragma unroll
            for (int q = 0; q < 4; q++) acc[i][j][q] = 0.f;

    issueLoads(0, 0);
    if (nIter > 1) issueLoads(1, BK);

    for (int it = 0; it < nIter; it++) {
        int buf = it % NS;
        if (it + 2 < nIter) {
            issueLoads((it + 2) % NS, (it + 2) * BK);
            cp_wait<2>();
        } else if (it + 1 < nIter) {
            cp_wait<1>();
        } else {
            cp_wait<0>();
        }
        __syncthreads();

        #pragma unroll
        for (int ks = 0; ks < 4; ks++) {
            unsigned af[4][4];
            #pragma unroll
            for (int mi = 0; mi < 4; mi++) {
                int row = wm + mi * 16 + (lm_i & 1) * 8 + lm_r;
                int chunk = ks * 2 + (lm_i >> 1);
                ldsm4(af[mi][0], af[mi][1], af[mi][2], af[mi][3],
                      sA + buf * ABYTES + fsw(row, chunk));
            }
            #pragma unroll
            for (int njp = 0; njp < NJP; njp++) {
                unsigned bb[4];
                int row = wn + njp * 16 + (lm_i >> 1) * 8 + lm_r;
                int chunk = ks * 2 + (lm_i & 1);
                ldsm4(bb[0], bb[1], bb[2], bb[3],
                      sB + buf * BBYTES + fsw(row, chunk));
                #pragma unroll
                for (int mi = 0; mi < 4; mi++) {
                    mma_f16(acc[mi][2 * njp],     af[mi], bb);
                    mma_f16(acc[mi][2 * njp + 1], af[mi], bb + 2);
                }
            }
        }
        __syncthreads();
    }

    #pragma unroll
    for (int mi = 0; mi < 4; mi++) {
        int row = bm + wm + mi * 16 + g;
        #pragma unroll
        for (int nj = 0; nj < NJ; nj++) {
            int col = bn + wn + nj * 8 + tig * 2;
            if (col >= N) continue;
            float v0 = acc[mi][nj][0];
            float v1 = acc[mi][nj][1];
            float v2 = acc[mi][nj][2];
            float v3 = acc[mi][nj][3];
            if (EPI >= 1) {
                float bb0 = bias[col];
                float bb1 = bias[col + 1];
                v0 += bb0; v1 += bb1; v2 += bb0; v3 += bb1;
            }
            if (EPI == 2) {
                v0 = fmaxf(v0, 0.f); v1 = fmaxf(v1, 0.f);
                v2 = fmaxf(v2, 0.f); v3 = fmaxf(v3, 0.f);
            }
            if (EPI == 3) {
                float2 a0 = *reinterpret_cast<const float2*>(aux + (long long)row * ldc + col);
                float2 a1 = *reinterpret_cast<const float2*>(aux + (long long)(row + 8) * ldc + col);
                v0 += a0.x; v1 += a0.y; v2 += a1.x; v3 += a1.y;
            }
            if (OUTH) {
                __half* C = (__half*)Cv;
                *reinterpret_cast<__half2*>(C + (long long)row * ldc + col) =
                    __floats2half2_rn(v0, v1);
                *reinterpret_cast<__half2*>(C + (long long)(row + 8) * ldc + col) =
                    __floats2half2_rn(v2, v3);
            } else {
                float* C = (float*)Cv;
                *reinterpret_cast<float2*>(C + (long long)row * ldc + col)       = make_float2(v0, v1);
                *reinterpret_cast<float2*>(C + (long long)(row + 8) * ldc + col) = make_float2(v2, v3);
            }
        }
    }
}

#define SMEM128 (NS * (BM + 128) * 128)   // 98304
#define SMEM64  (NS * (BM + 64) * 128)    // 73728

extern "C" void kernel_launch(void* const* d_in, const int* in_sizes, int n_in,
                              void* d_out, int out_size) {
    const int*   idx     = (const int*)d_in[0];
    const float* tok_emb = (const float*)d_in[1];
    const float* pos_emb = (const float*)d_in[2];
    const float* wq      = (const float*)d_in[3];
    const float* wk      = (const float*)d_in[4];
    const float* wv      = (const float*)d_in[5];
    const float* w_proj  = (const float*)d_in[6];
    const float* b_proj  = (const float*)d_in[7];
    const float* w1      = (const float*)d_in[8];
    const float* b1      = (const float*)d_in[9];
    const float* w2      = (const float*)d_in[10];
    const float* b2      = (const float*)d_in[11];
    const float* ln1_g   = (const float*)d_in[12];
    const float* ln1_b   = (const float*)d_in[13];
    const float* ln2_g   = (const float*)d_in[14];
    const float* ln2_b   = (const float*)d_in[15];
    const float* lnf_g   = (const float*)d_in[16];
    const float* lnf_b   = (const float*)d_in[17];
    const float* w_lm    = (const float*)d_in[18];
    const float* b_lm    = (const float*)d_in[19];
    float* out = (float*)d_out;

    float  *px, *psa;
    __half *ph, *pqkv, *pattn, *pff1;
    __half *pwqkvT, *pwprojT, *pw1T, *pw2T, *pwlmT;
    cudaGetSymbolAddress((void**)&px,      g_x);
    cudaGetSymbolAddress((void**)&ph,      g_h);
    cudaGetSymbolAddress((void**)&pqkv,    g_qkv);
    cudaGetSymbolAddress((void**)&pattn,   g_attn);
    cudaGetSymbolAddress((void**)&psa,     g_sa);
    cudaGetSymbolAddress((void**)&pff1,    g_ff1);
    cudaGetSymbolAddress((void**)&pwqkvT,  g_wqkvT);
    cudaGetSymbolAddress((void**)&pwprojT, g_wprojT);
    cudaGetSymbolAddress((void**)&pw1T,    g_w1T);
    cudaGetSymbolAddress((void**)&pw2T,    g_w2T);
    cudaGetSymbolAddress((void**)&pwlmT,   g_wlmT);

    // opt-in to >48KB dynamic smem (host-side, idempotent, capture-safe)
    cudaFuncSetAttribute(mma_gemm<0,true,128>,  cudaFuncAttributeMaxDynamicSharedMemorySize, SMEM128);
    cudaFuncSetAttribute(mma_gemm<2,true,128>,  cudaFuncAttributeMaxDynamicSharedMemorySize, SMEM128);
    cudaFuncSetAttribute(mma_gemm<1,false,128>, cudaFuncAttributeMaxDynamicSharedMemorySize, SMEM128);
    cudaFuncSetAttribute(mma_gemm<1,false,64>,  cudaFuncAttributeMaxDynamicSharedMemorySize, SMEM64);
    cudaFuncSetAttribute(mma_gemm<3,false,64>,  cudaFuncAttributeMaxDynamicSharedMemorySize, SMEM64);

    // ---- weight prep: transpose + fp16 cvt (half2 writes, fused qkv) ----
    {
        dim3 th(32, 8);
        pack_qkv_all<<<dim3(HDD/32, DD/64, 3*LL*HH), th>>>(wq, wk, wv);
        transpose_cvt2<<<dim3(DD/32,  DD/64,  LL), th>>>(w_proj, pwprojT, DD,  DD);
        transpose_cvt2<<<dim3(FFD/32, DD/64,  LL), th>>>(w1,     pw1T,    DD,  FFD);
        transpose_cvt2<<<dim3(DD/32,  FFD/64, LL), th>>>(w2,     pw2T,    FFD, DD);
        transpose_cvt2<<<dim3(VV/32,  DD/64,  1),  th>>>(w_lm,   pwlmT,   DD,  VV);
    }
    embed_kernel<<<BT, 256>>>(idx, tok_emb, pos_emb);

    for (int l = 0; l < LL; l++) {
        ln_kernel<<<BT, 256>>>(px, ln1_g + (long long)l*DD, ln1_b + (long long)l*DD, ph);

        // qkv = h @ wqkvT^T  -> fp16
        mma_gemm<0,true,128><<<dim3(BT/BM, 3*DD/128), 128, SMEM128>>>(
            ph, pwqkvT + (long long)l*3*DD*DD, nullptr, nullptr, pqkv,
            BT, 3*DD, DD, DD, DD, 3*DD);

        // vT per head
        v_transpose<<<dim3(TT/32, HDD/32, BB*HH), dim3(32, 8)>>>();

        // fused attention -> g_attn
        flash_attn<<<dim3(TT/FBR, BB*HH), 128>>>();

        // sa = attn @ w_proj + b_proj -> fp32  (BN=64: single wave)
        mma_gemm<1,false,64><<<dim3(BT/BM, DD/64), 128, SMEM64>>>(
            pattn, pwprojT + (long long)l*DD*DD, b_proj + (long long)l*DD, nullptr, psa,
            BT, DD, DD, DD, DD, DD);

        ln_kernel<<<BT, 256>>>(px, ln2_g + (long long)l*DD, ln2_b + (long long)l*DD, ph);

        // ff1 = relu(h @ w1 + b1) -> fp16
        mma_gemm<2,true,128><<<dim3(BT/BM, FFD/128), 128, SMEM128>>>(
            ph, pw1T + (long long)l*FFD*DD, b1 + (long long)l*FFD, nullptr, pff1,
            BT, FFD, DD, DD, DD, FFD);

        // x = ff1 @ w2 + b2 + sa  (residual fused) -> fp32  (BN=64)
        mma_gemm<3,false,64><<<dim3(BT/BM, DD/64), 128, SMEM64>>>(
            pff1, pw2T + (long long)l*DD*FFD, b2 + (long long)l*DD, psa, px,
            BT, DD, FFD, FFD, FFD, DD);
    }

    ln_kernel<<<BT, 256>>>(px, lnf_g, lnf_b, ph);

    // logits = h @ w_lm + b_lm -> fp32
    mma_gemm<1,false,128><<<dim3(BT/BM, VV/128), 128, SMEM128>>>(
        ph, pwlmT, b_lm, nullptr, out,
        BT, VV, DD, DD, DD, VV);
}